// round 2
// baseline (speedup 1.0000x reference)
#include <cuda_runtime.h>
#include <cuda_bf16.h>
#include <cstdint>

#define NN 100000
#define NE 1600000
#define D  128
#define NL 3

// ---- scratch (static device globals; no runtime allocation) ----
__device__ int   g_deg[NN];
__device__ float g_inv[NN];
__device__ int   g_rowptr[NN + 1];
__device__ int   g_cursor[NN];
__device__ int   g_esrc[NE];
__device__ float g_x[NN * D];      // layer ping
__device__ float g_y[NN * D];      // layer pong
__device__ float g_neigh[NN * D];  // mean-aggregated neighbor features

// ---------------------------------------------------------------
__global__ void k_zero_deg() {
    int i = blockIdx.x * blockDim.x + threadIdx.x;
    if (i < NN) g_deg[i] = 0;
}

__global__ void k_count(const int* __restrict__ dst) {
    int e = blockIdx.x * blockDim.x + threadIdx.x;
    if (e < NE) atomicAdd(&g_deg[dst[e]], 1);
}

// Single-block exclusive scan over g_deg -> g_rowptr; also inv-deg + cursor init.
__global__ void k_scan() {
    __shared__ int part[1024];
    int t = threadIdx.x;
    const int C = (NN + 1023) / 1024;  // 98
    int beg = t * C;
    int end = min(beg + C, NN);
    int s = 0;
    for (int i = beg; i < end; i++) s += g_deg[i];
    part[t] = s;
    __syncthreads();
    for (int off = 1; off < 1024; off <<= 1) {
        int v = (t >= off) ? part[t - off] : 0;
        __syncthreads();
        if (t >= off) part[t] += v;
        __syncthreads();
    }
    int run = (t == 0) ? 0 : part[t - 1];
    for (int i = beg; i < end; i++) {
        int d = g_deg[i];
        g_rowptr[i] = run;
        g_cursor[i] = run;
        g_inv[i]    = 1.0f / (float)max(d, 1);
        run += d;
    }
    if (t == 1023) g_rowptr[NN] = part[1023];
}

__global__ void k_fill(const int* __restrict__ src, const int* __restrict__ dst) {
    int e = blockIdx.x * blockDim.x + threadIdx.x;
    if (e < NE) {
        int p = atomicAdd(&g_cursor[dst[e]], 1);
        g_esrc[p] = src[e];
    }
}

// One warp per destination node. lane holds one float4 (128 floats across warp).
__global__ void k_agg(const float4* __restrict__ xin) {
    int w    = (blockIdx.x * blockDim.x + threadIdx.x) >> 5;
    int lane = threadIdx.x & 31;
    if (w >= NN) return;
    int beg = g_rowptr[w];
    int end = g_rowptr[w + 1];
    float4 a0 = make_float4(0.f, 0.f, 0.f, 0.f);
    float4 a1 = make_float4(0.f, 0.f, 0.f, 0.f);
    int e = beg;
    for (; e + 1 < end; e += 2) {
        int s0 = g_esrc[e];
        int s1 = g_esrc[e + 1];
        float4 v0 = __ldg(xin + (long)s0 * 32 + lane);
        float4 v1 = __ldg(xin + (long)s1 * 32 + lane);
        a0.x += v0.x; a0.y += v0.y; a0.z += v0.z; a0.w += v0.w;
        a1.x += v1.x; a1.y += v1.y; a1.z += v1.z; a1.w += v1.w;
    }
    if (e < end) {
        int s0 = g_esrc[e];
        float4 v0 = __ldg(xin + (long)s0 * 32 + lane);
        a0.x += v0.x; a0.y += v0.y; a0.z += v0.z; a0.w += v0.w;
    }
    float iv = g_inv[w];
    float4 r;
    r.x = (a0.x + a1.x) * iv;
    r.y = (a0.y + a1.y) * iv;
    r.z = (a0.z + a1.z) * iv;
    r.w = (a0.w + a1.w) * iv;
    ((float4*)g_neigh)[(long)w * 32 + lane] = r;
}

// ---------------- TF32x3 tensor-core GEMM -----------------------
// out[128 rows x 128 cols per block] = relu?( x@Ws + neigh@Wn + b )
// K = 256 (concat of x and neigh), k-chunk 32, 8 warps, warp tile 32x64.
// Full-precision recovery: acc += Ahi*Bhi + Ahi*Blo + Alo*Bhi  (tf32x3)

__device__ __forceinline__ uint32_t f2tf32(float x) {
    uint32_t r;
    asm("cvt.rna.tf32.f32 %0, %1;" : "=r"(r) : "f"(x));
    return r;
}

__device__ __forceinline__ void mma_tf32(float* c,
                                         uint32_t a0, uint32_t a1, uint32_t a2, uint32_t a3,
                                         uint32_t b0, uint32_t b1) {
    asm volatile(
        "mma.sync.aligned.m16n8k8.row.col.f32.tf32.tf32.f32 "
        "{%0,%1,%2,%3}, {%4,%5,%6,%7}, {%8,%9}, {%0,%1,%2,%3};\n"
        : "+f"(c[0]), "+f"(c[1]), "+f"(c[2]), "+f"(c[3])
        : "r"(a0), "r"(a1), "r"(a2), "r"(a3), "r"(b0), "r"(b1));
}

#define PITCH 20  // float2 pitch per row (16 pairs + 4 pad -> conflict-free LDS.64)

__global__ void __launch_bounds__(256, 2) k_gemm(
    const float* __restrict__ xin, float* __restrict__ out,
    const float* __restrict__ Wself, const float* __restrict__ Wneigh,
    const float* __restrict__ bias, int layer, int do_relu)
{
    // pair-packed full-fp32 tiles: element .x = v[k], .y = v[k+4]
    __shared__ float2 As2[128][PITCH];  // 20 KB
    __shared__ float2 Bs2[128][PITCH];  // 20 KB

    const int t    = threadIdx.x;
    const int warp = t >> 5;
    const int lane = t & 31;
    const int grp  = lane >> 2;   // 0..7
    const int tig  = lane & 3;    // 0..3
    const int warpRow = (warp >> 1) * 32;   // 0,32,64,96
    const int warpCol = (warp & 1) * 64;    // 0,64
    const int rowBase = blockIdx.x * 128;

    float acc[2][8][4];
#pragma unroll
    for (int i = 0; i < 2; i++)
#pragma unroll
        for (int j = 0; j < 8; j++)
#pragma unroll
            for (int q = 0; q < 4; q++) acc[i][j][q] = 0.f;

    const float* Wl_s = Wself  + (long)layer * D * D;
    const float* Wl_n = Wneigh + (long)layer * D * D;

    for (int kc = 0; kc < 8; kc++) {
        const float* Xsrc = (kc < 4) ? xin  : g_neigh;
        const float* Wsrc = (kc < 4) ? Wl_s : Wl_n;
        const int koff = (kc & 3) * 32;

        // ---- stage A tile [128 rows x 32 k] (pair-packed) ----
#pragma unroll
        for (int idx = t; idx < 128 * 8; idx += 256) {
            int r = idx >> 3, q = idx & 7;           // q-th float4 in the 32-k row
            int row = rowBase + r;
            float4 v = make_float4(0.f, 0.f, 0.f, 0.f);
            if (row < NN)
                v = *(const float4*)(Xsrc + (long)row * D + koff + q * 4);
            float* base = (float*)As2[r];
            int pbase = 4 * (q >> 1), slot = q & 1;
            base[(pbase + 0) * 2 + slot] = v.x;
            base[(pbase + 1) * 2 + slot] = v.y;
            base[(pbase + 2) * 2 + slot] = v.z;
            base[(pbase + 3) * 2 + slot] = v.w;
        }
        // ---- stage B tile: W[koff..+31][0..127] -> Bs2[n][pair] (transpose) ----
#pragma unroll
        for (int idx = t; idx < 32 * 32; idx += 256) {
            int k = idx >> 5, n4 = idx & 31;
            float4 v = *(const float4*)(Wsrc + (long)(koff + k) * D + n4 * 4);
            int pair = (k & 3) + 4 * (k >> 3), slot = (k >> 2) & 1;
            ((float*)Bs2[n4 * 4 + 0])[pair * 2 + slot] = v.x;
            ((float*)Bs2[n4 * 4 + 1])[pair * 2 + slot] = v.y;
            ((float*)Bs2[n4 * 4 + 2])[pair * 2 + slot] = v.z;
            ((float*)Bs2[n4 * 4 + 3])[pair * 2 + slot] = v.w;
        }
        __syncthreads();

        // ---- compute: 4 k-steps of 8 ----
#pragma unroll
        for (int ks = 0; ks < 4; ks++) {
            const int pair = 4 * ks + tig;
            uint32_t ahi[2][4], alo[2][4];
#pragma unroll
            for (int ma = 0; ma < 2; ma++) {
                int r0 = warpRow + ma * 16 + grp;
                float2 p0 = As2[r0][pair];       // (a0, a2)
                float2 p1 = As2[r0 + 8][pair];   // (a1, a3)
                ahi[ma][0] = f2tf32(p0.x);
                ahi[ma][1] = f2tf32(p1.x);
                ahi[ma][2] = f2tf32(p0.y);
                ahi[ma][3] = f2tf32(p1.y);
                alo[ma][0] = f2tf32(p0.x - __uint_as_float(ahi[ma][0]));
                alo[ma][1] = f2tf32(p1.x - __uint_as_float(ahi[ma][1]));
                alo[ma][2] = f2tf32(p0.y - __uint_as_float(ahi[ma][2]));
                alo[ma][3] = f2tf32(p1.y - __uint_as_float(ahi[ma][3]));
            }
#pragma unroll
            for (int na = 0; na < 8; na++) {
                int n = warpCol + na * 8 + grp;
                float2 bp = Bs2[n][pair];        // (b0, b1)
                uint32_t bh0 = f2tf32(bp.x);
                uint32_t bh1 = f2tf32(bp.y);
                uint32_t bl0 = f2tf32(bp.x - __uint_as_float(bh0));
                uint32_t bl1 = f2tf32(bp.y - __uint_as_float(bh1));
#pragma unroll
                for (int ma = 0; ma < 2; ma++) {
                    mma_tf32(acc[ma][na], ahi[ma][0], ahi[ma][1], ahi[ma][2], ahi[ma][3], bh0, bh1);
                    mma_tf32(acc[ma][na], ahi[ma][0], ahi[ma][1], ahi[ma][2], ahi[ma][3], bl0, bl1);
                    mma_tf32(acc[ma][na], alo[ma][0], alo[ma][1], alo[ma][2], alo[ma][3], bh0, bh1);
                }
            }
        }
        __syncthreads();
    }

    // ---- epilogue: bias (+relu), float2 stores ----
    const float* bl = bias + (long)layer * D;
#pragma unroll
    for (int na = 0; na < 8; na++) {
        int col = warpCol + na * 8 + tig * 2;
        float2 bv = *(const float2*)(bl + col);
#pragma unroll
        for (int ma = 0; ma < 2; ma++) {
            int r0 = rowBase + warpRow + ma * 16 + grp;
            float* c = acc[ma][na];
            float2 o0, o1;
            o0.x = c[0] + bv.x; o0.y = c[1] + bv.y;
            o1.x = c[2] + bv.x; o1.y = c[3] + bv.y;
            if (do_relu) {
                o0.x = fmaxf(o0.x, 0.f); o0.y = fmaxf(o0.y, 0.f);
                o1.x = fmaxf(o1.x, 0.f); o1.y = fmaxf(o1.y, 0.f);
            }
            if (r0 < NN)     *(float2*)(out + (long)r0 * D + col)       = o0;
            if (r0 + 8 < NN) *(float2*)(out + (long)(r0 + 8) * D + col) = o1;
        }
    }
}

// ---------------------------------------------------------------
extern "C" void kernel_launch(void* const* d_in, const int* in_sizes, int n_in,
                              void* d_out, int out_size) {
    const float* emb = (const float*)d_in[0];
    const float* Ws  = (const float*)d_in[1];
    const float* Wn  = (const float*)d_in[2];
    const float* b   = (const float*)d_in[3];
    const int*   src = (const int*)d_in[4];
    const int*   dst = (const int*)d_in[5];
    float*       out = (float*)d_out;

    void *px, *py;
    cudaGetSymbolAddress(&px, g_x);
    cudaGetSymbolAddress(&py, g_y);
    float* xbuf = (float*)px;
    float* ybuf = (float*)py;

    // CSR build (once per launch)
    k_zero_deg<<<(NN + 255) / 256, 256>>>();
    k_count<<<(NE + 255) / 256, 256>>>(dst);
    k_scan<<<1, 1024>>>();
    k_fill<<<(NE + 255) / 256, 256>>>(src, dst);

    const int aggGrid  = (NN + 7) / 8;      // 8 warps per 256-thread block
    const int gemmGrid = (NN + 127) / 128;  // 782

    // layer 0: emb -> g_x   (relu)
    k_agg<<<aggGrid, 256>>>((const float4*)emb);
    k_gemm<<<gemmGrid, 256>>>(emb, xbuf, Ws, Wn, b, 0, 1);

    // layer 1: g_x -> g_y   (relu)
    k_agg<<<aggGrid, 256>>>((const float4*)xbuf);
    k_gemm<<<gemmGrid, 256>>>(xbuf, ybuf, Ws, Wn, b, 1, 1);

    // layer 2: g_y -> d_out (no relu)
    k_agg<<<aggGrid, 256>>>((const float4*)ybuf);
    k_gemm<<<gemmGrid, 256>>>(ybuf, out, Ws, Wn, b, 2, 0);
}

// round 4
// speedup vs baseline: 1.5615x; 1.5615x over previous
#include <cuda_runtime.h>
#include <cuda_bf16.h>
#include <cstdint>

#define NN 100000
#define NE 1600000
#define D  128
#define KK 256   // concat(x, neigh)

// ---- scratch (static device globals; no runtime allocation) ----
__device__ int   g_deg[NN];
__device__ float g_inv[NN];
__device__ int   g_rowptr[NN + 1];
__device__ int   g_cursor[NN];
__device__ int   g_esrc[NE];
__device__ float g_x[NN * D];                 // fp32 x after layer 0 (agg input)
__device__ float g_y[NN * D];                 // fp32 x after layer 1
__device__ __nv_bfloat16 g_Ah[(size_t)NN * KK];  // GEMM A operand, hi half
__device__ __nv_bfloat16 g_Al[(size_t)NN * KK];  // GEMM A operand, lo half
__device__ __nv_bfloat16 g_Wh[3 * D * KK];    // W^T concat, [layer][n][k] hi
__device__ __nv_bfloat16 g_Wl[3 * D * KK];    // lo

// ================= helpers =================
__device__ __forceinline__ uint32_t smem_u32(const void* p) {
    uint32_t a;
    asm("{ .reg .u64 t; cvta.to.shared.u64 t, %1; cvt.u32.u64 %0, t; }"
        : "=r"(a) : "l"(p));
    return a;
}
__device__ __forceinline__ void hilo(float v, __nv_bfloat16& h, __nv_bfloat16& l) {
    h = __float2bfloat16(v);
    l = __float2bfloat16(v - __bfloat162float(h));
}
#define LDSM4(d0, d1, d2, d3, addr)                                         \
    asm volatile("ldmatrix.sync.aligned.m8n8.x4.shared.b16 {%0,%1,%2,%3}, [%4];" \
                 : "=r"(d0), "=r"(d1), "=r"(d2), "=r"(d3) : "r"(addr))

__device__ __forceinline__ void mma_bf16(float* c, const uint32_t* a,
                                         uint32_t b0, uint32_t b1) {
    asm volatile(
        "mma.sync.aligned.m16n8k16.row.col.f32.bf16.bf16.f32 "
        "{%0,%1,%2,%3}, {%4,%5,%6,%7}, {%8,%9}, {%0,%1,%2,%3};\n"
        : "+f"(c[0]), "+f"(c[1]), "+f"(c[2]), "+f"(c[3])
        : "r"(a[0]), "r"(a[1]), "r"(a[2]), "r"(a[3]), "r"(b0), "r"(b1));
}

// ================= one-time conversions =================
// W concat transpose: Wt[l][n][k] (k = 0..127 self, 128..255 neigh), hi/lo bf16
__global__ void k_cvtw(const float* __restrict__ Ws, const float* __restrict__ Wn) {
    int id = blockIdx.x * blockDim.x + threadIdx.x;   // 3*256*128
    if (id >= 3 * KK * D) return;
    int n = id & (D - 1);
    int k = (id >> 7) & (KK - 1);
    int l = id >> 15;
    float v = (k < D) ? Ws[(l * D + k) * D + n] : Wn[(l * D + (k - D)) * D + n];
    __nv_bfloat16 h, lo;
    hilo(v, h, lo);
    int o = (l * D + n) * KK + k;
    g_Wh[o] = h;
    g_Wl[o] = lo;
}

// emb fp32 -> A cols 0..127 (hi/lo)
__global__ void k_cvtx(const float4* __restrict__ x4) {
    int id = blockIdx.x * blockDim.x + threadIdx.x;  // NN*32
    if (id >= NN * 32) return;
    int row = id >> 5, j = id & 31;
    float4 v = x4[id];
    __nv_bfloat16 hx, hy, hz, hw, lx, ly, lz, lw;
    hilo(v.x, hx, lx); hilo(v.y, hy, ly);
    hilo(v.z, hz, lz); hilo(v.w, hw, lw);
    size_t o = (size_t)row * KK + j * 4;
    *(__nv_bfloat162*)(g_Ah + o)     = __nv_bfloat162(hx, hy);
    *(__nv_bfloat162*)(g_Ah + o + 2) = __nv_bfloat162(hz, hw);
    *(__nv_bfloat162*)(g_Al + o)     = __nv_bfloat162(lx, ly);
    *(__nv_bfloat162*)(g_Al + o + 2) = __nv_bfloat162(lz, lw);
}

// ================= CSR build =================
__global__ void k_zero_deg() {
    int i = blockIdx.x * blockDim.x + threadIdx.x;
    if (i < NN) g_deg[i] = 0;
}
__global__ void k_count(const int* __restrict__ dst) {
    int e = blockIdx.x * blockDim.x + threadIdx.x;
    if (e < NE) atomicAdd(&g_deg[dst[e]], 1);
}
__global__ void k_scan() {
    __shared__ int part[1024];
    int t = threadIdx.x;
    const int C = (NN + 1023) / 1024;
    int beg = t * C, end = min(beg + C, NN);
    int s = 0;
    for (int i = beg; i < end; i++) s += g_deg[i];
    part[t] = s;
    __syncthreads();
    for (int off = 1; off < 1024; off <<= 1) {
        int v = (t >= off) ? part[t - off] : 0;
        __syncthreads();
        if (t >= off) part[t] += v;
        __syncthreads();
    }
    int run = (t == 0) ? 0 : part[t - 1];
    for (int i = beg; i < end; i++) {
        int d = g_deg[i];
        g_rowptr[i] = run;
        g_cursor[i] = run;
        g_inv[i]    = 1.0f / (float)max(d, 1);
        run += d;
    }
    if (t == 1023) g_rowptr[NN] = part[1023];
}
__global__ void k_fill(const int* __restrict__ src, const int* __restrict__ dst) {
    int e = blockIdx.x * blockDim.x + threadIdx.x;
    if (e < NE) {
        int p = atomicAdd(&g_cursor[dst[e]], 1);
        g_esrc[p] = src[e];
    }
}

// ================= aggregation (warp per node, MLP=4) =================
// writes bf16 hi/lo mean-neighbor directly into A cols 128..255
__global__ void k_agg(const float4* __restrict__ xin) {
    int w    = (blockIdx.x * blockDim.x + threadIdx.x) >> 5;
    int lane = threadIdx.x & 31;
    if (w >= NN) return;
    int beg = g_rowptr[w];
    int end = g_rowptr[w + 1];
    float4 a0 = make_float4(0.f, 0.f, 0.f, 0.f);
    float4 a1 = make_float4(0.f, 0.f, 0.f, 0.f);
    float4 a2 = make_float4(0.f, 0.f, 0.f, 0.f);
    float4 a3 = make_float4(0.f, 0.f, 0.f, 0.f);
    int e = beg;
    for (; e + 3 < end; e += 4) {
        int s0 = g_esrc[e], s1 = g_esrc[e + 1], s2 = g_esrc[e + 2], s3 = g_esrc[e + 3];
        float4 v0 = __ldg(xin + (long)s0 * 32 + lane);
        float4 v1 = __ldg(xin + (long)s1 * 32 + lane);
        float4 v2 = __ldg(xin + (long)s2 * 32 + lane);
        float4 v3 = __ldg(xin + (long)s3 * 32 + lane);
        a0.x += v0.x; a0.y += v0.y; a0.z += v0.z; a0.w += v0.w;
        a1.x += v1.x; a1.y += v1.y; a1.z += v1.z; a1.w += v1.w;
        a2.x += v2.x; a2.y += v2.y; a2.z += v2.z; a2.w += v2.w;
        a3.x += v3.x; a3.y += v3.y; a3.z += v3.z; a3.w += v3.w;
    }
    for (; e < end; e++) {
        int s0 = g_esrc[e];
        float4 v0 = __ldg(xin + (long)s0 * 32 + lane);
        a0.x += v0.x; a0.y += v0.y; a0.z += v0.z; a0.w += v0.w;
    }
    float iv = g_inv[w];
    float rx = (a0.x + a1.x + a2.x + a3.x) * iv;
    float ry = (a0.y + a1.y + a2.y + a3.y) * iv;
    float rz = (a0.z + a1.z + a2.z + a3.z) * iv;
    float rw = (a0.w + a1.w + a2.w + a3.w) * iv;
    __nv_bfloat16 hx, hy, hz, hw, lx, ly, lz, lw;
    hilo(rx, hx, lx); hilo(ry, hy, ly);
    hilo(rz, hz, lz); hilo(rw, hw, lw);
    size_t o = (size_t)w * KK + D + lane * 4;
    *(__nv_bfloat162*)(g_Ah + o)     = __nv_bfloat162(hx, hy);
    *(__nv_bfloat162*)(g_Ah + o + 2) = __nv_bfloat162(hz, hw);
    *(__nv_bfloat162*)(g_Al + o)     = __nv_bfloat162(lx, ly);
    *(__nv_bfloat162*)(g_Al + o + 2) = __nv_bfloat162(lz, lw);
}

// ================= bf16x3 HMMA GEMM =================
// block: 128x128 out, 8 warps (4 row-groups x 2 col-groups), warp 32x64.
// K=256 in 8 chunks of 32; smem pitch 40 bf16 (80 B) -> conflict-free ldmatrix.
#define PIT 40
__global__ void __launch_bounds__(256, 2) k_gemm(
    float* __restrict__ out, const float* __restrict__ bias,
    int layer, int do_relu, int write_bf)
{
    __shared__ __nv_bfloat16 sAh[128][PIT];
    __shared__ __nv_bfloat16 sAl[128][PIT];
    __shared__ __nv_bfloat16 sBh[128][PIT];
    __shared__ __nv_bfloat16 sBl[128][PIT];

    const int t    = threadIdx.x;
    const int warp = t >> 5;
    const int lane = t & 31;
    const int warpRow = (warp >> 1) * 32;
    const int warpCol = (warp & 1) * 64;
    const long rowBase = (long)blockIdx.x * 128;

    const uint32_t saAh = smem_u32(sAh);
    const uint32_t saAl = smem_u32(sAl);
    const uint32_t saBh = smem_u32(sBh);
    const uint32_t saBl = smem_u32(sBl);

    const int jq = lane >> 3;   // matrix index 0..3
    const int rr = lane & 7;

    float acc[2][8][4];
#pragma unroll
    for (int i = 0; i < 2; i++)
#pragma unroll
        for (int j = 0; j < 8; j++)
#pragma unroll
            for (int q = 0; q < 4; q++) acc[i][j][q] = 0.f;

    const __nv_bfloat16* gW_h = g_Wh + (size_t)layer * D * KK;
    const __nv_bfloat16* gW_l = g_Wl + (size_t)layer * D * KK;

    for (int kc = 0; kc < 8; kc++) {
        const int koff = kc * 32;
        // ---- stage A tiles (hi/lo): 128 rows x 32 k = 512 uint4 each ----
#pragma unroll
        for (int i = 0; i < 2; i++) {
            int idx = t + i * 256;
            int r = idx >> 2, q = idx & 3;
            long row = rowBase + r;
            uint4 vh = make_uint4(0, 0, 0, 0), vl = make_uint4(0, 0, 0, 0);
            if (row < NN) {
                const uint4* ph = (const uint4*)(g_Ah + row * KK + koff);
                const uint4* pl = (const uint4*)(g_Al + row * KK + koff);
                vh = ph[q];
                vl = pl[q];
            }
            *(uint4*)(&sAh[r][q * 8]) = vh;
            *(uint4*)(&sAl[r][q * 8]) = vl;
        }
        // ---- stage B tiles (hi/lo): 128 n x 32 k ----
#pragma unroll
        for (int i = 0; i < 2; i++) {
            int idx = t + i * 256;
            int n = idx >> 2, q = idx & 3;
            const uint4* ph = (const uint4*)(gW_h + (size_t)n * KK + koff);
            const uint4* pl = (const uint4*)(gW_l + (size_t)n * KK + koff);
            *(uint4*)(&sBh[n][q * 8]) = ph[q];
            *(uint4*)(&sBl[n][q * 8]) = pl[q];
        }
        __syncthreads();

#pragma unroll
        for (int ks = 0; ks < 2; ks++) {
            const int k0 = ks * 16;
            // A fragments: hi & lo for both m-atoms
            uint32_t ah[2][4], al[2][4];
#pragma unroll
            for (int ma = 0; ma < 2; ma++) {
                uint32_t off = (uint32_t)((warpRow + ma * 16 + (jq & 1) * 8 + rr) * (PIT * 2)
                                          + (k0 + (jq >> 1) * 8) * 2);
                LDSM4(ah[ma][0], ah[ma][1], ah[ma][2], ah[ma][3], saAh + off);
                LDSM4(al[ma][0], al[ma][1], al[ma][2], al[ma][3], saAl + off);
            }
            // B groups of 16 n
#pragma unroll
            for (int g = 0; g < 4; g++) {
                uint32_t boff = (uint32_t)((warpCol + g * 16 + (jq >> 1) * 8 + rr) * (PIT * 2)
                                           + (k0 + (jq & 1) * 8) * 2);
                uint32_t bh[4], bl[4];
                LDSM4(bh[0], bh[1], bh[2], bh[3], saBh + boff);
                LDSM4(bl[0], bl[1], bl[2], bl[3], saBl + boff);
#pragma unroll
                for (int sub = 0; sub < 2; sub++) {
                    int na = g * 2 + sub;
                    uint32_t b0h = bh[sub * 2], b1h = bh[sub * 2 + 1];
                    uint32_t b0l = bl[sub * 2], b1l = bl[sub * 2 + 1];
#pragma unroll
                    for (int ma = 0; ma < 2; ma++) {
                        mma_bf16(acc[ma][na], ah[ma], b0h, b1h);
                        mma_bf16(acc[ma][na], ah[ma], b0l, b1l);
                        mma_bf16(acc[ma][na], al[ma], b0h, b1h);
                    }
                }
            }
        }
        __syncthreads();
    }

    // ---- epilogue: bias (+relu); fp32 out; optional bf16 hi/lo x for next layer ----
    const float* bl = bias + (size_t)layer * D;
    const int q2 = (lane & 3) * 2;
    const int rq = lane >> 2;
#pragma unroll
    for (int na = 0; na < 8; na++) {
        int col = warpCol + na * 8 + q2;
        float2 bv = *(const float2*)(bl + col);
#pragma unroll
        for (int ma = 0; ma < 2; ma++) {
            float* c = acc[ma][na];
            long r0 = rowBase + warpRow + ma * 16 + rq;
#pragma unroll
            for (int h = 0; h < 2; h++) {   // h=0: rows rq, h=1: rq+8 (c2,c3)
                long row = r0 + h * 8;
                if (row >= NN) continue;
                float ox = c[h * 2 + 0] + bv.x;
                float oy = c[h * 2 + 1] + bv.y;
                if (do_relu) { ox = fmaxf(ox, 0.f); oy = fmaxf(oy, 0.f); }
                *(float2*)(out + row * D + col) = make_float2(ox, oy);
                if (write_bf) {
                    __nv_bfloat16 hx, hy, lx, ly;
                    hilo(ox, hx, lx);
                    hilo(oy, hy, ly);
                    size_t o = (size_t)row * KK + col;
                    *(__nv_bfloat162*)(g_Ah + o) = __nv_bfloat162(hx, hy);
                    *(__nv_bfloat162*)(g_Al + o) = __nv_bfloat162(lx, ly);
                }
            }
        }
    }
}

// ---------------------------------------------------------------
extern "C" void kernel_launch(void* const* d_in, const int* in_sizes, int n_in,
                              void* d_out, int out_size) {
    const float* emb = (const float*)d_in[0];
    const float* Ws  = (const float*)d_in[1];
    const float* Wn  = (const float*)d_in[2];
    const float* b   = (const float*)d_in[3];
    const int*   src = (const int*)d_in[4];
    const int*   dst = (const int*)d_in[5];
    float*       out = (float*)d_out;

    void *px, *py;
    cudaGetSymbolAddress(&px, g_x);
    cudaGetSymbolAddress(&py, g_y);
    float* xbuf = (float*)px;
    float* ybuf = (float*)py;

    // one-time conversions + CSR build
    k_cvtw<<<(3 * KK * D + 255) / 256, 256>>>(Ws, Wn);
    k_cvtx<<<(NN * 32 + 255) / 256, 256>>>((const float4*)emb);
    k_zero_deg<<<(NN + 255) / 256, 256>>>();
    k_count<<<(NE + 255) / 256, 256>>>(dst);
    k_scan<<<1, 1024>>>();
    k_fill<<<(NE + 255) / 256, 256>>>(src, dst);

    const int aggGrid  = (NN + 7) / 8;
    const int gemmGrid = (NN + 127) / 128;

    // layer 0: A = [emb | agg(emb)]  -> g_x (+ A cols 0..127)
    k_agg<<<aggGrid, 256>>>((const float4*)emb);
    k_gemm<<<gemmGrid, 256>>>(xbuf, b, 0, 1, 1);

    // layer 1
    k_agg<<<aggGrid, 256>>>((const float4*)xbuf);
    k_gemm<<<gemmGrid, 256>>>(ybuf, b, 1, 1, 1);

    // layer 2 -> d_out (no relu, no bf16 writeback)
    k_agg<<<aggGrid, 256>>>((const float4*)ybuf);
    k_gemm<<<gemmGrid, 256>>>(out, b, 2, 0, 0);
}

// round 5
// speedup vs baseline: 1.6576x; 1.0616x over previous
#include <cuda_runtime.h>
#include <cuda_bf16.h>
#include <cstdint>

#define NN 100000
#define NE 1600000
#define D  128
#define KK 256   // concat(x, neigh)

// ---- scratch (static device globals; no runtime allocation) ----
__device__ int   g_deg[NN];
__device__ float g_inv[NN];
__device__ int   g_rowptr[NN + 1];
__device__ int   g_cursor[NN];
__device__ int   g_esrc[NE];
__device__ float g_x[NN * D];
__device__ float g_y[NN * D];
__device__ __nv_bfloat16 g_Ah[(size_t)NN * KK];
__device__ __nv_bfloat16 g_Al[(size_t)NN * KK];
__device__ __nv_bfloat16 g_Wh[3 * D * KK];
__device__ __nv_bfloat16 g_Wl[3 * D * KK];

// ================= helpers =================
__device__ __forceinline__ uint32_t smem_u32(const void* p) {
    uint32_t a;
    asm("{ .reg .u64 t; cvta.to.shared.u64 t, %1; cvt.u32.u64 %0, t; }"
        : "=r"(a) : "l"(p));
    return a;
}
__device__ __forceinline__ void hilo(float v, __nv_bfloat16& h, __nv_bfloat16& l) {
    h = __float2bfloat16(v);
    l = __float2bfloat16(v - __bfloat162float(h));
}
#define LDSM4(d0, d1, d2, d3, addr)                                         \
    asm volatile("ldmatrix.sync.aligned.m8n8.x4.shared.b16 {%0,%1,%2,%3}, [%4];" \
                 : "=r"(d0), "=r"(d1), "=r"(d2), "=r"(d3) : "r"(addr))

__device__ __forceinline__ void mma_bf16(float* c, const uint32_t* a,
                                         uint32_t b0, uint32_t b1) {
    asm volatile(
        "mma.sync.aligned.m16n8k16.row.col.f32.bf16.bf16.f32 "
        "{%0,%1,%2,%3}, {%4,%5,%6,%7}, {%8,%9}, {%0,%1,%2,%3};\n"
        : "+f"(c[0]), "+f"(c[1]), "+f"(c[2]), "+f"(c[3])
        : "r"(a[0]), "r"(a[1]), "r"(a[2]), "r"(a[3]), "r"(b0), "r"(b1));
}

#define CP_ASYNC(dst, src, sz)                                              \
    asm volatile("cp.async.cg.shared.global [%0], [%1], 16, %2;"            \
                 :: "r"(dst), "l"(src), "r"(sz))
#define CP_COMMIT() asm volatile("cp.async.commit_group;" ::: "memory")
#define CP_WAIT1()  asm volatile("cp.async.wait_group 1;" ::: "memory")
#define CP_WAIT0()  asm volatile("cp.async.wait_group 0;" ::: "memory")

// swizzled byte offset of 16B chunk c of row r inside an 8KB tile (64B rows)
__device__ __forceinline__ uint32_t swz(int r, int c) {
    return (uint32_t)(r * 64 + ((c ^ ((r >> 1) & 3)) << 4));
}

// ================= one-time conversions =================
__global__ void k_cvtw(const float* __restrict__ Ws, const float* __restrict__ Wn) {
    int id = blockIdx.x * blockDim.x + threadIdx.x;
    if (id >= 3 * KK * D) return;
    int n = id & (D - 1);
    int k = (id >> 7) & (KK - 1);
    int l = id >> 15;
    float v = (k < D) ? Ws[(l * D + k) * D + n] : Wn[(l * D + (k - D)) * D + n];
    __nv_bfloat16 h, lo;
    hilo(v, h, lo);
    int o = (l * D + n) * KK + k;
    g_Wh[o] = h;
    g_Wl[o] = lo;
}

__global__ void k_cvtx(const float4* __restrict__ x4) {
    int id = blockIdx.x * blockDim.x + threadIdx.x;
    if (id >= NN * 32) return;
    int row = id >> 5, j = id & 31;
    float4 v = x4[id];
    __nv_bfloat16 hx, hy, hz, hw, lx, ly, lz, lw;
    hilo(v.x, hx, lx); hilo(v.y, hy, ly);
    hilo(v.z, hz, lz); hilo(v.w, hw, lw);
    size_t o = (size_t)row * KK + j * 4;
    *(__nv_bfloat162*)(g_Ah + o)     = __nv_bfloat162(hx, hy);
    *(__nv_bfloat162*)(g_Ah + o + 2) = __nv_bfloat162(hz, hw);
    *(__nv_bfloat162*)(g_Al + o)     = __nv_bfloat162(lx, ly);
    *(__nv_bfloat162*)(g_Al + o + 2) = __nv_bfloat162(lz, lw);
}

// ================= CSR build =================
__global__ void k_count(const int* __restrict__ dst) {
    int e = blockIdx.x * blockDim.x + threadIdx.x;
    if (e < NE) atomicAdd(&g_deg[dst[e]], 1);
}
__global__ void k_scan() {
    __shared__ int part[1024];
    int t = threadIdx.x;
    const int C = (NN + 1023) / 1024;
    int beg = t * C, end = min(beg + C, NN);
    int s = 0;
    for (int i = beg; i < end; i++) s += g_deg[i];
    part[t] = s;
    __syncthreads();
    for (int off = 1; off < 1024; off <<= 1) {
        int v = (t >= off) ? part[t - off] : 0;
        __syncthreads();
        if (t >= off) part[t] += v;
        __syncthreads();
    }
    int run = (t == 0) ? 0 : part[t - 1];
    for (int i = beg; i < end; i++) {
        int d = g_deg[i];
        g_rowptr[i] = run;
        g_cursor[i] = run;
        g_inv[i]    = 1.0f / (float)max(d, 1);
        run += d;
    }
    if (t == 1023) g_rowptr[NN] = part[1023];
}
__global__ void k_fill(const int* __restrict__ src, const int* __restrict__ dst) {
    int e = blockIdx.x * blockDim.x + threadIdx.x;
    if (e < NE) {
        int p = atomicAdd(&g_cursor[dst[e]], 1);
        g_esrc[p] = src[e];
    }
}

// ================= aggregation (warp per node, MLP=4) =================
__global__ void k_agg(const float4* __restrict__ xin) {
    int w    = (blockIdx.x * blockDim.x + threadIdx.x) >> 5;
    int lane = threadIdx.x & 31;
    if (w >= NN) return;
    int beg = g_rowptr[w];
    int end = g_rowptr[w + 1];
    float4 a0 = make_float4(0.f, 0.f, 0.f, 0.f);
    float4 a1 = make_float4(0.f, 0.f, 0.f, 0.f);
    float4 a2 = make_float4(0.f, 0.f, 0.f, 0.f);
    float4 a3 = make_float4(0.f, 0.f, 0.f, 0.f);
    int e = beg;
    for (; e + 3 < end; e += 4) {
        int s0 = g_esrc[e], s1 = g_esrc[e + 1], s2 = g_esrc[e + 2], s3 = g_esrc[e + 3];
        float4 v0 = __ldg(xin + (long)s0 * 32 + lane);
        float4 v1 = __ldg(xin + (long)s1 * 32 + lane);
        float4 v2 = __ldg(xin + (long)s2 * 32 + lane);
        float4 v3 = __ldg(xin + (long)s3 * 32 + lane);
        a0.x += v0.x; a0.y += v0.y; a0.z += v0.z; a0.w += v0.w;
        a1.x += v1.x; a1.y += v1.y; a1.z += v1.z; a1.w += v1.w;
        a2.x += v2.x; a2.y += v2.y; a2.z += v2.z; a2.w += v2.w;
        a3.x += v3.x; a3.y += v3.y; a3.z += v3.z; a3.w += v3.w;
    }
    for (; e < end; e++) {
        int s0 = g_esrc[e];
        float4 v0 = __ldg(xin + (long)s0 * 32 + lane);
        a0.x += v0.x; a0.y += v0.y; a0.z += v0.z; a0.w += v0.w;
    }
    float iv = g_inv[w];
    float rx = (a0.x + a1.x + a2.x + a3.x) * iv;
    float ry = (a0.y + a1.y + a2.y + a3.y) * iv;
    float rz = (a0.z + a1.z + a2.z + a3.z) * iv;
    float rw = (a0.w + a1.w + a2.w + a3.w) * iv;
    __nv_bfloat16 hx, hy, hz, hw, lx, ly, lz, lw;
    hilo(rx, hx, lx); hilo(ry, hy, ly);
    hilo(rz, hz, lz); hilo(rw, hw, lw);
    size_t o = (size_t)w * KK + D + lane * 4;
    *(__nv_bfloat162*)(g_Ah + o)     = __nv_bfloat162(hx, hy);
    *(__nv_bfloat162*)(g_Ah + o + 2) = __nv_bfloat162(hz, hw);
    *(__nv_bfloat162*)(g_Al + o)     = __nv_bfloat162(lx, ly);
    *(__nv_bfloat162*)(g_Al + o + 2) = __nv_bfloat162(lz, lw);
}

// ================= bf16x3 HMMA GEMM, cp.async 3-stage pipeline =================
// block 128x128 out; 8 warps (4 row-grp x 2 col-grp), warp 32x64; K=256 / 8 chunks of 32.
// dyn smem: 3 stages x [Ah 8K | Al 8K | Bh 8K | Bl 8K] = 96KB.
#define STAGE_SZ 32768
#define T_AL 8192
#define T_BH 16384
#define T_BL 24576

extern __shared__ __align__(16) uint8_t dynsm[];

__global__ void __launch_bounds__(256, 2) k_gemm(
    float* __restrict__ out, const float* __restrict__ bias,
    int layer, int do_relu, int write_bf)
{
    const int t    = threadIdx.x;
    const int warp = t >> 5;
    const int lane = t & 31;
    const int warpRow = (warp >> 1) * 32;
    const int warpCol = (warp & 1) * 64;
    const long rowBase = (long)blockIdx.x * 128;

    const uint32_t sbase = smem_u32(dynsm);
    const int jq = lane >> 3;
    const int rr = lane & 7;

    const __nv_bfloat16* gW_h = g_Wh + (size_t)layer * D * KK;
    const __nv_bfloat16* gW_l = g_Wl + (size_t)layer * D * KK;

    // staging indices for this thread: 2 chunks per tile-array
    const int r0s = (t + 0)   >> 2, c0s = (t + 0)   & 3;
    const int r1s = (t + 256) >> 2, c1s = (t + 256) & 3;

    float acc[2][8][4];
#pragma unroll
    for (int i = 0; i < 2; i++)
#pragma unroll
        for (int j = 0; j < 8; j++)
#pragma unroll
            for (int q = 0; q < 4; q++) acc[i][j][q] = 0.f;

    // ---- issue one stage's cp.asyncs ----
    auto issue = [&](int kc, int stage) {
        const uint32_t base = sbase + stage * STAGE_SZ;
        const int koff = kc * 32;
#pragma unroll
        for (int i = 0; i < 2; i++) {
            const int r = i ? r1s : r0s;
            const int c = i ? c1s : c0s;
            long row = rowBase + r;
            uint32_t sz = (row < NN) ? 16u : 0u;
            long arow = (row < NN) ? row : 0;
            const void* pAh = g_Ah + arow * KK + koff + c * 8;
            const void* pAl = g_Al + arow * KK + koff + c * 8;
            const void* pBh = gW_h + (size_t)r * KK + koff + c * 8;
            const void* pBl = gW_l + (size_t)r * KK + koff + c * 8;
            uint32_t o = swz(r, c);
            CP_ASYNC(base + o,        pAh, sz);
            CP_ASYNC(base + o + T_AL, pAl, sz);
            CP_ASYNC(base + o + T_BH, pBh, 16u);
            CP_ASYNC(base + o + T_BL, pBl, 16u);
        }
        CP_COMMIT();
    };

    issue(0, 0);

    for (int kc = 0; kc < 8; kc++) {
        const int stage = kc % 3;
        if (kc < 7) issue(kc + 1, (kc + 1) % 3);
        if (kc < 7) { CP_WAIT1(); } else { CP_WAIT0(); }
        __syncthreads();

        const uint32_t base = sbase + stage * STAGE_SZ;
#pragma unroll
        for (int ks = 0; ks < 2; ks++) {
            uint32_t ah[2][4], al[2][4];
#pragma unroll
            for (int ma = 0; ma < 2; ma++) {
                int ra = warpRow + ma * 16 + (jq & 1) * 8 + rr;
                int ca = ks * 2 + (jq >> 1);
                uint32_t off = swz(ra, ca);
                LDSM4(ah[ma][0], ah[ma][1], ah[ma][2], ah[ma][3], base + off);
                LDSM4(al[ma][0], al[ma][1], al[ma][2], al[ma][3], base + off + T_AL);
            }
#pragma unroll
            for (int g = 0; g < 4; g++) {
                int rb = warpCol + g * 16 + (jq >> 1) * 8 + rr;
                int cb = ks * 2 + (jq & 1);
                uint32_t boff = swz(rb, cb);
                uint32_t bh[4], bl[4];
                LDSM4(bh[0], bh[1], bh[2], bh[3], base + boff + T_BH);
                LDSM4(bl[0], bl[1], bl[2], bl[3], base + boff + T_BL);
#pragma unroll
                for (int sub = 0; sub < 2; sub++) {
                    int na = g * 2 + sub;
                    uint32_t b0h = bh[sub * 2], b1h = bh[sub * 2 + 1];
                    uint32_t b0l = bl[sub * 2], b1l = bl[sub * 2 + 1];
#pragma unroll
                    for (int ma = 0; ma < 2; ma++) {
                        mma_bf16(acc[ma][na], ah[ma], b0h, b1h);
                        mma_bf16(acc[ma][na], ah[ma], b0l, b1l);
                        mma_bf16(acc[ma][na], al[ma], b0h, b1h);
                    }
                }
            }
        }
        __syncthreads();
    }

    // ---- epilogue ----
    const float* bl = bias + (size_t)layer * D;
    const int q2 = (lane & 3) * 2;
    const int rq = lane >> 2;
#pragma unroll
    for (int na = 0; na < 8; na++) {
        int col = warpCol + na * 8 + q2;
        float2 bv = *(const float2*)(bl + col);
#pragma unroll
        for (int ma = 0; ma < 2; ma++) {
            float* c = acc[ma][na];
            long r0 = rowBase + warpRow + ma * 16 + rq;
#pragma unroll
            for (int h = 0; h < 2; h++) {
                long row = r0 + h * 8;
                if (row >= NN) continue;
                float ox = c[h * 2 + 0] + bv.x;
                float oy = c[h * 2 + 1] + bv.y;
                if (do_relu) { ox = fmaxf(ox, 0.f); oy = fmaxf(oy, 0.f); }
                *(float2*)(out + row * D + col) = make_float2(ox, oy);
                if (write_bf) {
                    __nv_bfloat16 hx, hy, lx, ly;
                    hilo(ox, hx, lx);
                    hilo(oy, hy, ly);
                    size_t o = (size_t)row * KK + col;
                    *(__nv_bfloat162*)(g_Ah + o) = __nv_bfloat162(hx, hy);
                    *(__nv_bfloat162*)(g_Al + o) = __nv_bfloat162(lx, ly);
                }
            }
        }
    }
}

// ---------------------------------------------------------------
extern "C" void kernel_launch(void* const* d_in, const int* in_sizes, int n_in,
                              void* d_out, int out_size) {
    const float* emb = (const float*)d_in[0];
    const float* Ws  = (const float*)d_in[1];
    const float* Wn  = (const float*)d_in[2];
    const float* b   = (const float*)d_in[3];
    const int*   src = (const int*)d_in[4];
    const int*   dst = (const int*)d_in[5];
    float*       out = (float*)d_out;

    void *px, *py, *pdeg;
    cudaGetSymbolAddress(&px, g_x);
    cudaGetSymbolAddress(&py, g_y);
    cudaGetSymbolAddress(&pdeg, g_deg);
    float* xbuf = (float*)px;
    float* ybuf = (float*)py;

    cudaFuncSetAttribute(k_gemm, cudaFuncAttributeMaxDynamicSharedMemorySize,
                         3 * STAGE_SZ);

    // one-time conversions + CSR build
    k_cvtw<<<(3 * KK * D + 255) / 256, 256>>>(Ws, Wn);
    k_cvtx<<<(NN * 32 + 255) / 256, 256>>>((const float4*)emb);
    cudaMemsetAsync(pdeg, 0, NN * sizeof(int));
    k_count<<<(NE + 255) / 256, 256>>>(dst);
    k_scan<<<1, 1024>>>();
    k_fill<<<(NE + 255) / 256, 256>>>(src, dst);

    const int aggGrid  = (NN + 7) / 8;
    const int gemmGrid = (NN + 127) / 128;

    k_agg<<<aggGrid, 256>>>((const float4*)emb);
    k_gemm<<<gemmGrid, 256, 3 * STAGE_SZ>>>(xbuf, b, 0, 1, 1);

    k_agg<<<aggGrid, 256>>>((const float4*)xbuf);
    k_gemm<<<gemmGrid, 256, 3 * STAGE_SZ>>>(ybuf, b, 1, 1, 1);

    k_agg<<<aggGrid, 256>>>((const float4*)ybuf);
    k_gemm<<<gemmGrid, 256, 3 * STAGE_SZ>>>(out, b, 2, 0, 0);
}

// round 6
// speedup vs baseline: 2.3821x; 1.4370x over previous
#include <cuda_runtime.h>
#include <cuda_bf16.h>
#include <cstdint>

#define NN 100000
#define NE 1600000
#define D  128
#define KK 256   // concat(x, neigh)

#define SCAN_NB ((NN + 255) / 256)   // 391

// ---- scratch (static device globals; no runtime allocation) ----
__device__ int   g_deg[NN];
__device__ float g_inv[NN];
__device__ int   g_rowptr[NN + 1];
__device__ int   g_cursor[NN];
__device__ int   g_esrc[NE];
__device__ int   g_part[SCAN_NB];
__device__ int   g_pscan[SCAN_NB];
__device__ float g_x[NN * D];
__device__ float g_y[NN * D];
__device__ __nv_bfloat16 g_Ah[(size_t)NN * KK];
__device__ __nv_bfloat16 g_Al[(size_t)NN * KK];
__device__ __nv_bfloat16 g_Wh[3 * D * KK];
__device__ __nv_bfloat16 g_Wl[3 * D * KK];

// ================= helpers =================
__device__ __forceinline__ uint32_t smem_u32(const void* p) {
    uint32_t a;
    asm("{ .reg .u64 t; cvta.to.shared.u64 t, %1; cvt.u32.u64 %0, t; }"
        : "=r"(a) : "l"(p));
    return a;
}
__device__ __forceinline__ void hilo(float v, __nv_bfloat16& h, __nv_bfloat16& l) {
    h = __float2bfloat16(v);
    l = __float2bfloat16(v - __bfloat162float(h));
}
#define LDSM4(d0, d1, d2, d3, addr)                                         \
    asm volatile("ldmatrix.sync.aligned.m8n8.x4.shared.b16 {%0,%1,%2,%3}, [%4];" \
                 : "=r"(d0), "=r"(d1), "=r"(d2), "=r"(d3) : "r"(addr))

__device__ __forceinline__ void mma_bf16(float* c, const uint32_t* a,
                                         uint32_t b0, uint32_t b1) {
    asm volatile(
        "mma.sync.aligned.m16n8k16.row.col.f32.bf16.bf16.f32 "
        "{%0,%1,%2,%3}, {%4,%5,%6,%7}, {%8,%9}, {%0,%1,%2,%3};\n"
        : "+f"(c[0]), "+f"(c[1]), "+f"(c[2]), "+f"(c[3])
        : "r"(a[0]), "r"(a[1]), "r"(a[2]), "r"(a[3]), "r"(b0), "r"(b1));
}

#define CP_ASYNC(dst, src, sz)                                              \
    asm volatile("cp.async.cg.shared.global [%0], [%1], 16, %2;"            \
                 :: "r"(dst), "l"(src), "r"(sz))
#define CP_COMMIT() asm volatile("cp.async.commit_group;" ::: "memory")
#define CP_WAIT1()  asm volatile("cp.async.wait_group 1;" ::: "memory")
#define CP_WAIT0()  asm volatile("cp.async.wait_group 0;" ::: "memory")

__device__ __forceinline__ uint32_t swz(int r, int c) {
    return (uint32_t)(r * 64 + ((c ^ ((r >> 1) & 3)) << 4));
}

// ================= one-time conversions =================
__global__ void k_cvtw(const float* __restrict__ Ws, const float* __restrict__ Wn) {
    int id = blockIdx.x * blockDim.x + threadIdx.x;
    if (id >= 3 * KK * D) return;
    int n = id & (D - 1);
    int k = (id >> 7) & (KK - 1);
    int l = id >> 15;
    float v = (k < D) ? Ws[(l * D + k) * D + n] : Wn[(l * D + (k - D)) * D + n];
    __nv_bfloat16 h, lo;
    hilo(v, h, lo);
    int o = (l * D + n) * KK + k;
    g_Wh[o] = h;
    g_Wl[o] = lo;
}

__global__ void k_cvtx(const float4* __restrict__ x4) {
    int id = blockIdx.x * blockDim.x + threadIdx.x;
    if (id >= NN * 32) return;
    int row = id >> 5, j = id & 31;
    float4 v = x4[id];
    __nv_bfloat16 hx, hy, hz, hw, lx, ly, lz, lw;
    hilo(v.x, hx, lx); hilo(v.y, hy, ly);
    hilo(v.z, hz, lz); hilo(v.w, hw, lw);
    size_t o = (size_t)row * KK + j * 4;
    *(__nv_bfloat162*)(g_Ah + o)     = __nv_bfloat162(hx, hy);
    *(__nv_bfloat162*)(g_Ah + o + 2) = __nv_bfloat162(hz, hw);
    *(__nv_bfloat162*)(g_Al + o)     = __nv_bfloat162(lx, ly);
    *(__nv_bfloat162*)(g_Al + o + 2) = __nv_bfloat162(lz, lw);
}

// ================= CSR build =================
__global__ void k_count(const int* __restrict__ dst) {
    int e = blockIdx.x * blockDim.x + threadIdx.x;
    if (e < NE) atomicAdd(&g_deg[dst[e]], 1);
}

// phase 1: per-block (256 nodes) sum of degrees
__global__ void k_part() {
    int i = blockIdx.x * 256 + threadIdx.x;
    int lane = threadIdx.x & 31, warp = threadIdx.x >> 5;
    int v = (i < NN) ? g_deg[i] : 0;
#pragma unroll
    for (int off = 16; off > 0; off >>= 1)
        v += __shfl_down_sync(0xFFFFFFFFu, v, off);
    __shared__ int ws[8];
    if (lane == 0) ws[warp] = v;
    __syncthreads();
    if (threadIdx.x < 8) {
        int s = ws[threadIdx.x];
#pragma unroll
        for (int off = 4; off > 0; off >>= 1)
            s += __shfl_down_sync(0xFFu, s, off);
        if (threadIdx.x == 0) g_part[blockIdx.x] = s;
    }
}

// phase 2: single block scans the 391 partials (exclusive)
__global__ void k_scanp() {
    __shared__ int sp[512];
    int t = threadIdx.x;
    sp[t] = (t < SCAN_NB) ? g_part[t] : 0;
    __syncthreads();
#pragma unroll
    for (int off = 1; off < 512; off <<= 1) {
        int v = (t >= off) ? sp[t - off] : 0;
        __syncthreads();
        sp[t] += v;
        __syncthreads();
    }
    if (t < SCAN_NB) g_pscan[t] = (t == 0) ? 0 : sp[t - 1];
}

// phase 3: block-local exclusive scan + base; write rowptr/cursor/inv
__global__ void k_write() {
    int i = blockIdx.x * 256 + threadIdx.x;
    int lane = threadIdx.x & 31, warp = threadIdx.x >> 5;
    int d = (i < NN) ? g_deg[i] : 0;
    int x = d;
#pragma unroll
    for (int off = 1; off < 32; off <<= 1) {
        int y = __shfl_up_sync(0xFFFFFFFFu, x, off);
        if (lane >= off) x += y;
    }
    __shared__ int ws[8];
    if (lane == 31) ws[warp] = x;
    __syncthreads();
    if (warp == 0 && lane < 8) {
        int s = ws[lane];
#pragma unroll
        for (int off = 1; off < 8; off <<= 1) {
            int y = __shfl_up_sync(0xFFu, s, off);
            if (lane >= off) s += y;
        }
        ws[lane] = s;
    }
    __syncthreads();
    int base = g_pscan[blockIdx.x] + ((warp == 0) ? 0 : ws[warp - 1]);
    int excl = base + x - d;
    if (i < NN) {
        g_rowptr[i] = excl;
        g_cursor[i] = excl;
        g_inv[i]    = 1.0f / (float)max(d, 1);
        if (i == NN - 1) g_rowptr[NN] = excl + d;
    }
}

__global__ void k_fill(const int* __restrict__ src, const int* __restrict__ dst) {
    int e = blockIdx.x * blockDim.x + threadIdx.x;
    if (e < NE) {
        int p = atomicAdd(&g_cursor[dst[e]], 1);
        g_esrc[p] = src[e];
    }
}

// ================= aggregation (warp per node, MLP=4) =================
__global__ void k_agg(const float4* __restrict__ xin) {
    int w    = (blockIdx.x * blockDim.x + threadIdx.x) >> 5;
    int lane = threadIdx.x & 31;
    if (w >= NN) return;
    int beg = g_rowptr[w];
    int end = g_rowptr[w + 1];
    float4 a0 = make_float4(0.f, 0.f, 0.f, 0.f);
    float4 a1 = make_float4(0.f, 0.f, 0.f, 0.f);
    float4 a2 = make_float4(0.f, 0.f, 0.f, 0.f);
    float4 a3 = make_float4(0.f, 0.f, 0.f, 0.f);
    int e = beg;
    for (; e + 3 < end; e += 4) {
        int s0 = g_esrc[e], s1 = g_esrc[e + 1], s2 = g_esrc[e + 2], s3 = g_esrc[e + 3];
        float4 v0 = __ldg(xin + (long)s0 * 32 + lane);
        float4 v1 = __ldg(xin + (long)s1 * 32 + lane);
        float4 v2 = __ldg(xin + (long)s2 * 32 + lane);
        float4 v3 = __ldg(xin + (long)s3 * 32 + lane);
        a0.x += v0.x; a0.y += v0.y; a0.z += v0.z; a0.w += v0.w;
        a1.x += v1.x; a1.y += v1.y; a1.z += v1.z; a1.w += v1.w;
        a2.x += v2.x; a2.y += v2.y; a2.z += v2.z; a2.w += v2.w;
        a3.x += v3.x; a3.y += v3.y; a3.z += v3.z; a3.w += v3.w;
    }
    for (; e < end; e++) {
        int s0 = g_esrc[e];
        float4 v0 = __ldg(xin + (long)s0 * 32 + lane);
        a0.x += v0.x; a0.y += v0.y; a0.z += v0.z; a0.w += v0.w;
    }
    float iv = g_inv[w];
    float rx = (a0.x + a1.x + a2.x + a3.x) * iv;
    float ry = (a0.y + a1.y + a2.y + a3.y) * iv;
    float rz = (a0.z + a1.z + a2.z + a3.z) * iv;
    float rw = (a0.w + a1.w + a2.w + a3.w) * iv;
    __nv_bfloat16 hx, hy, hz, hw, lx, ly, lz, lw;
    hilo(rx, hx, lx); hilo(ry, hy, ly);
    hilo(rz, hz, lz); hilo(rw, hw, lw);
    size_t o = (size_t)w * KK + D + lane * 4;
    *(__nv_bfloat162*)(g_Ah + o)     = __nv_bfloat162(hx, hy);
    *(__nv_bfloat162*)(g_Ah + o + 2) = __nv_bfloat162(hz, hw);
    *(__nv_bfloat162*)(g_Al + o)     = __nv_bfloat162(lx, ly);
    *(__nv_bfloat162*)(g_Al + o + 2) = __nv_bfloat162(lz, lw);
}

// ================= bf16x3 HMMA GEMM, cp.async 3-stage pipeline =================
#define STAGE_SZ 32768
#define T_AL 8192
#define T_BH 16384
#define T_BL 24576

extern __shared__ __align__(16) uint8_t dynsm[];

__global__ void __launch_bounds__(256, 2) k_gemm(
    float* __restrict__ out, const float* __restrict__ bias,
    int layer, int do_relu, int write_bf)
{
    const int t    = threadIdx.x;
    const int warp = t >> 5;
    const int lane = t & 31;
    const int warpRow = (warp >> 1) * 32;
    const int warpCol = (warp & 1) * 64;
    const long rowBase = (long)blockIdx.x * 128;

    const uint32_t sbase = smem_u32(dynsm);
    const int jq = lane >> 3;
    const int rr = lane & 7;

    const __nv_bfloat16* gW_h = g_Wh + (size_t)layer * D * KK;
    const __nv_bfloat16* gW_l = g_Wl + (size_t)layer * D * KK;

    const int r0s = (t + 0)   >> 2, c0s = (t + 0)   & 3;
    const int r1s = (t + 256) >> 2, c1s = (t + 256) & 3;

    float acc[2][8][4];
#pragma unroll
    for (int i = 0; i < 2; i++)
#pragma unroll
        for (int j = 0; j < 8; j++)
#pragma unroll
            for (int q = 0; q < 4; q++) acc[i][j][q] = 0.f;

    auto issue = [&](int kc, int stage) {
        const uint32_t base = sbase + stage * STAGE_SZ;
        const int koff = kc * 32;
#pragma unroll
        for (int i = 0; i < 2; i++) {
            const int r = i ? r1s : r0s;
            const int c = i ? c1s : c0s;
            long row = rowBase + r;
            uint32_t sz = (row < NN) ? 16u : 0u;
            long arow = (row < NN) ? row : 0;
            const void* pAh = g_Ah + arow * KK + koff + c * 8;
            const void* pAl = g_Al + arow * KK + koff + c * 8;
            const void* pBh = gW_h + (size_t)r * KK + koff + c * 8;
            const void* pBl = gW_l + (size_t)r * KK + koff + c * 8;
            uint32_t o = swz(r, c);
            CP_ASYNC(base + o,        pAh, sz);
            CP_ASYNC(base + o + T_AL, pAl, sz);
            CP_ASYNC(base + o + T_BH, pBh, 16u);
            CP_ASYNC(base + o + T_BL, pBl, 16u);
        }
        CP_COMMIT();
    };

    issue(0, 0);

    for (int kc = 0; kc < 8; kc++) {
        const int stage = kc % 3;
        if (kc < 7) issue(kc + 1, (kc + 1) % 3);
        if (kc < 7) { CP_WAIT1(); } else { CP_WAIT0(); }
        __syncthreads();

        const uint32_t base = sbase + stage * STAGE_SZ;
#pragma unroll
        for (int ks = 0; ks < 2; ks++) {
            uint32_t ah[2][4], al[2][4];
#pragma unroll
            for (int ma = 0; ma < 2; ma++) {
                int ra = warpRow + ma * 16 + (jq & 1) * 8 + rr;
                int ca = ks * 2 + (jq >> 1);
                uint32_t off = swz(ra, ca);
                LDSM4(ah[ma][0], ah[ma][1], ah[ma][2], ah[ma][3], base + off);
                LDSM4(al[ma][0], al[ma][1], al[ma][2], al[ma][3], base + off + T_AL);
            }
#pragma unroll
            for (int g = 0; g < 4; g++) {
                int rb = warpCol + g * 16 + (jq >> 1) * 8 + rr;
                int cb = ks * 2 + (jq & 1);
                uint32_t boff = swz(rb, cb);
                uint32_t bh[4], bl[4];
                LDSM4(bh[0], bh[1], bh[2], bh[3], base + boff + T_BH);
                LDSM4(bl[0], bl[1], bl[2], bl[3], base + boff + T_BL);
#pragma unroll
                for (int sub = 0; sub < 2; sub++) {
                    int na = g * 2 + sub;
                    uint32_t b0h = bh[sub * 2], b1h = bh[sub * 2 + 1];
                    uint32_t b0l = bl[sub * 2], b1l = bl[sub * 2 + 1];
#pragma unroll
                    for (int ma = 0; ma < 2; ma++) {
                        mma_bf16(acc[ma][na], ah[ma], b0h, b1h);
                        mma_bf16(acc[ma][na], ah[ma], b0l, b1l);
                        mma_bf16(acc[ma][na], al[ma], b0h, b1h);
                    }
                }
            }
        }
        __syncthreads();
    }

    const float* bl = bias + (size_t)layer * D;
    const int q2 = (lane & 3) * 2;
    const int rq = lane >> 2;
#pragma unroll
    for (int na = 0; na < 8; na++) {
        int col = warpCol + na * 8 + q2;
        float2 bv = *(const float2*)(bl + col);
#pragma unroll
        for (int ma = 0; ma < 2; ma++) {
            float* c = acc[ma][na];
            long r0 = rowBase + warpRow + ma * 16 + rq;
#pragma unroll
            for (int h = 0; h < 2; h++) {
                long row = r0 + h * 8;
                if (row >= NN) continue;
                float ox = c[h * 2 + 0] + bv.x;
                float oy = c[h * 2 + 1] + bv.y;
                if (do_relu) { ox = fmaxf(ox, 0.f); oy = fmaxf(oy, 0.f); }
                *(float2*)(out + row * D + col) = make_float2(ox, oy);
                if (write_bf) {
                    __nv_bfloat16 hx, hy, lx, ly;
                    hilo(ox, hx, lx);
                    hilo(oy, hy, ly);
                    size_t o = (size_t)row * KK + col;
                    *(__nv_bfloat162*)(g_Ah + o) = __nv_bfloat162(hx, hy);
                    *(__nv_bfloat162*)(g_Al + o) = __nv_bfloat162(lx, ly);
                }
            }
        }
    }
}

// ---------------------------------------------------------------
extern "C" void kernel_launch(void* const* d_in, const int* in_sizes, int n_in,
                              void* d_out, int out_size) {
    const float* emb = (const float*)d_in[0];
    const float* Ws  = (const float*)d_in[1];
    const float* Wn  = (const float*)d_in[2];
    const float* b   = (const float*)d_in[3];
    const int*   src = (const int*)d_in[4];
    const int*   dst = (const int*)d_in[5];
    float*       out = (float*)d_out;

    void *px, *py, *pdeg;
    cudaGetSymbolAddress(&px, g_x);
    cudaGetSymbolAddress(&py, g_y);
    cudaGetSymbolAddress(&pdeg, g_deg);
    float* xbuf = (float*)px;
    float* ybuf = (float*)py;

    cudaFuncSetAttribute(k_gemm, cudaFuncAttributeMaxDynamicSharedMemorySize,
                         3 * STAGE_SZ);

    // one-time conversions + CSR build
    k_cvtw<<<(3 * KK * D + 255) / 256, 256>>>(Ws, Wn);
    k_cvtx<<<(NN * 32 + 255) / 256, 256>>>((const float4*)emb);
    cudaMemsetAsync(pdeg, 0, NN * sizeof(int));
    k_count<<<(NE + 255) / 256, 256>>>(dst);
    k_part<<<SCAN_NB, 256>>>();
    k_scanp<<<1, 512>>>();
    k_write<<<SCAN_NB, 256>>>();
    k_fill<<<(NE + 255) / 256, 256>>>(src, dst);

    const int aggGrid  = (NN + 7) / 8;
    const int gemmGrid = (NN + 127) / 128;

    k_agg<<<aggGrid, 256>>>((const float4*)emb);
    k_gemm<<<gemmGrid, 256, 3 * STAGE_SZ>>>(xbuf, b, 0, 1, 1);

    k_agg<<<aggGrid, 256>>>((const float4*)xbuf);
    k_gemm<<<gemmGrid, 256, 3 * STAGE_SZ>>>(ybuf, b, 1, 1, 1);

    k_agg<<<aggGrid, 256>>>((const float4*)ybuf);
    k_gemm<<<gemmGrid, 256, 3 * STAGE_SZ>>>(out, b, 2, 0, 0);
}

// round 7
// speedup vs baseline: 2.6866x; 1.1278x over previous
#include <cuda_runtime.h>
#include <cuda_bf16.h>
#include <cuda_fp16.h>
#include <cstdint>

#define NN 100000
#define NE 1600000
#define D  128
#define KK 256   // concat(x, neigh)

#define SCAN_NB ((NN + 255) / 256)   // 391

// ---- scratch (static device globals; no runtime allocation) ----
__device__ int   g_deg[NN];
__device__ float g_inv[NN];
__device__ int   g_rowptr[NN + 1];
__device__ int   g_cursor[NN];
__device__ int   g_esrc[NE];
__device__ int   g_part[SCAN_NB];
__device__ int   g_pscan[SCAN_NB];
__device__ __half g_hx[(size_t)NN * D];          // fp16 x table (agg gather)
__device__ __nv_bfloat16 g_Ah[(size_t)NN * KK];  // GEMM A hi
__device__ __nv_bfloat16 g_Al[(size_t)NN * KK];  // GEMM A lo
__device__ __nv_bfloat16 g_Wh[3 * D * KK];
__device__ __nv_bfloat16 g_Wl[3 * D * KK];

// ================= helpers =================
__device__ __forceinline__ uint32_t smem_u32(const void* p) {
    uint32_t a;
    asm("{ .reg .u64 t; cvta.to.shared.u64 t, %1; cvt.u32.u64 %0, t; }"
        : "=r"(a) : "l"(p));
    return a;
}
__device__ __forceinline__ void hilo(float v, __nv_bfloat16& h, __nv_bfloat16& l) {
    h = __float2bfloat16(v);
    l = __float2bfloat16(v - __bfloat162float(h));
}
#define LDSM4(d0, d1, d2, d3, addr)                                         \
    asm volatile("ldmatrix.sync.aligned.m8n8.x4.shared.b16 {%0,%1,%2,%3}, [%4];" \
                 : "=r"(d0), "=r"(d1), "=r"(d2), "=r"(d3) : "r"(addr))

__device__ __forceinline__ void mma_bf16(float* c, const uint32_t* a,
                                         uint32_t b0, uint32_t b1) {
    asm volatile(
        "mma.sync.aligned.m16n8k16.row.col.f32.bf16.bf16.f32 "
        "{%0,%1,%2,%3}, {%4,%5,%6,%7}, {%8,%9}, {%0,%1,%2,%3};\n"
        : "+f"(c[0]), "+f"(c[1]), "+f"(c[2]), "+f"(c[3])
        : "r"(a[0]), "r"(a[1]), "r"(a[2]), "r"(a[3]), "r"(b0), "r"(b1));
}

#define CP_ASYNC(dst, src, sz)                                              \
    asm volatile("cp.async.cg.shared.global [%0], [%1], 16, %2;"            \
                 :: "r"(dst), "l"(src), "r"(sz))
#define CP_COMMIT() asm volatile("cp.async.commit_group;" ::: "memory")
#define CP_WAIT1()  asm volatile("cp.async.wait_group 1;" ::: "memory")
#define CP_WAIT0()  asm volatile("cp.async.wait_group 0;" ::: "memory")

__device__ __forceinline__ uint32_t swz(int r, int c) {
    return (uint32_t)(r * 64 + ((c ^ ((r >> 1) & 3)) << 4));
}

// ================= one-time conversions =================
__global__ void k_cvtw(const float* __restrict__ Ws, const float* __restrict__ Wn) {
    int id = blockIdx.x * blockDim.x + threadIdx.x;
    if (id >= 3 * KK * D) return;
    int n = id & (D - 1);
    int k = (id >> 7) & (KK - 1);
    int l = id >> 15;
    float v = (k < D) ? Ws[(l * D + k) * D + n] : Wn[(l * D + (k - D)) * D + n];
    __nv_bfloat16 h, lo;
    hilo(v, h, lo);
    int o = (l * D + n) * KK + k;
    g_Wh[o] = h;
    g_Wl[o] = lo;
}

// emb fp32 -> A cols 0..127 (bf16 hi/lo) + fp16 gather table
__global__ void k_cvtx(const float4* __restrict__ x4) {
    int id = blockIdx.x * blockDim.x + threadIdx.x;
    if (id >= NN * 32) return;
    int row = id >> 5, j = id & 31;
    float4 v = x4[id];
    __nv_bfloat16 hx, hy, hz, hw, lx, ly, lz, lw;
    hilo(v.x, hx, lx); hilo(v.y, hy, ly);
    hilo(v.z, hz, lz); hilo(v.w, hw, lw);
    size_t o = (size_t)row * KK + j * 4;
    *(__nv_bfloat162*)(g_Ah + o)     = __nv_bfloat162(hx, hy);
    *(__nv_bfloat162*)(g_Ah + o + 2) = __nv_bfloat162(hz, hw);
    *(__nv_bfloat162*)(g_Al + o)     = __nv_bfloat162(lx, ly);
    *(__nv_bfloat162*)(g_Al + o + 2) = __nv_bfloat162(lz, lw);
    __half2* ph = (__half2*)(g_hx + (size_t)row * D + j * 4);
    ph[0] = __floats2half2_rn(v.x, v.y);
    ph[1] = __floats2half2_rn(v.z, v.w);
}

// ================= CSR build =================
__global__ void k_count(const int* __restrict__ dst) {
    int e = blockIdx.x * blockDim.x + threadIdx.x;
    if (e < NE) atomicAdd(&g_deg[dst[e]], 1);
}

__global__ void k_part() {
    int i = blockIdx.x * 256 + threadIdx.x;
    int lane = threadIdx.x & 31, warp = threadIdx.x >> 5;
    int v = (i < NN) ? g_deg[i] : 0;
#pragma unroll
    for (int off = 16; off > 0; off >>= 1)
        v += __shfl_down_sync(0xFFFFFFFFu, v, off);
    __shared__ int ws[8];
    if (lane == 0) ws[warp] = v;
    __syncthreads();
    if (threadIdx.x < 8) {
        int s = ws[threadIdx.x];
#pragma unroll
        for (int off = 4; off > 0; off >>= 1)
            s += __shfl_down_sync(0xFFu, s, off);
        if (threadIdx.x == 0) g_part[blockIdx.x] = s;
    }
}

__global__ void k_scanp() {
    __shared__ int sp[512];
    int t = threadIdx.x;
    sp[t] = (t < SCAN_NB) ? g_part[t] : 0;
    __syncthreads();
#pragma unroll
    for (int off = 1; off < 512; off <<= 1) {
        int v = (t >= off) ? sp[t - off] : 0;
        __syncthreads();
        sp[t] += v;
        __syncthreads();
    }
    if (t < SCAN_NB) g_pscan[t] = (t == 0) ? 0 : sp[t - 1];
}

__global__ void k_write() {
    int i = blockIdx.x * 256 + threadIdx.x;
    int lane = threadIdx.x & 31, warp = threadIdx.x >> 5;
    int d = (i < NN) ? g_deg[i] : 0;
    int x = d;
#pragma unroll
    for (int off = 1; off < 32; off <<= 1) {
        int y = __shfl_up_sync(0xFFFFFFFFu, x, off);
        if (lane >= off) x += y;
    }
    __shared__ int ws[8];
    if (lane == 31) ws[warp] = x;
    __syncthreads();
    if (warp == 0 && lane < 8) {
        int s = ws[lane];
#pragma unroll
        for (int off = 1; off < 8; off <<= 1) {
            int y = __shfl_up_sync(0xFFu, s, off);
            if (lane >= off) s += y;
        }
        ws[lane] = s;
    }
    __syncthreads();
    int base = g_pscan[blockIdx.x] + ((warp == 0) ? 0 : ws[warp - 1]);
    int excl = base + x - d;
    if (i < NN) {
        g_rowptr[i] = excl;
        g_cursor[i] = excl;
        g_inv[i]    = 1.0f / (float)max(d, 1);
        if (i == NN - 1) g_rowptr[NN] = excl + d;
    }
}

__global__ void k_fill(const int* __restrict__ src, const int* __restrict__ dst) {
    int e = blockIdx.x * blockDim.x + threadIdx.x;
    if (e < NE) {
        int p = atomicAdd(&g_cursor[dst[e]], 1);
        g_esrc[p] = src[e];
    }
}

// ================= aggregation: fp16 gather (256 B/row), fp32 accumulate ====
__global__ void k_agg() {
    int w    = (blockIdx.x * blockDim.x + threadIdx.x) >> 5;
    int lane = threadIdx.x & 31;
    if (w >= NN) return;
    int beg = g_rowptr[w];
    int end = g_rowptr[w + 1];
    float4 a0 = make_float4(0.f, 0.f, 0.f, 0.f);
    float4 a1 = make_float4(0.f, 0.f, 0.f, 0.f);
    float4 a2 = make_float4(0.f, 0.f, 0.f, 0.f);
    float4 a3 = make_float4(0.f, 0.f, 0.f, 0.f);
    const uint2* hx = (const uint2*)g_hx;   // 8 B = 4 halfs per lane-slot
    int e = beg;
    for (; e + 3 < end; e += 4) {
        int s0 = g_esrc[e], s1 = g_esrc[e + 1], s2 = g_esrc[e + 2], s3 = g_esrc[e + 3];
        uint2 u0 = __ldg(hx + (long)s0 * 32 + lane);
        uint2 u1 = __ldg(hx + (long)s1 * 32 + lane);
        uint2 u2 = __ldg(hx + (long)s2 * 32 + lane);
        uint2 u3 = __ldg(hx + (long)s3 * 32 + lane);
        float2 p, q;
        p = __half22float2(*(__half2*)&u0.x); q = __half22float2(*(__half2*)&u0.y);
        a0.x += p.x; a0.y += p.y; a0.z += q.x; a0.w += q.y;
        p = __half22float2(*(__half2*)&u1.x); q = __half22float2(*(__half2*)&u1.y);
        a1.x += p.x; a1.y += p.y; a1.z += q.x; a1.w += q.y;
        p = __half22float2(*(__half2*)&u2.x); q = __half22float2(*(__half2*)&u2.y);
        a2.x += p.x; a2.y += p.y; a2.z += q.x; a2.w += q.y;
        p = __half22float2(*(__half2*)&u3.x); q = __half22float2(*(__half2*)&u3.y);
        a3.x += p.x; a3.y += p.y; a3.z += q.x; a3.w += q.y;
    }
    for (; e < end; e++) {
        int s0 = g_esrc[e];
        uint2 u0 = __ldg(hx + (long)s0 * 32 + lane);
        float2 p = __half22float2(*(__half2*)&u0.x);
        float2 q = __half22float2(*(__half2*)&u0.y);
        a0.x += p.x; a0.y += p.y; a0.z += q.x; a0.w += q.y;
    }
    float iv = g_inv[w];
    float rx = (a0.x + a1.x + a2.x + a3.x) * iv;
    float ry = (a0.y + a1.y + a2.y + a3.y) * iv;
    float rz = (a0.z + a1.z + a2.z + a3.z) * iv;
    float rw = (a0.w + a1.w + a2.w + a3.w) * iv;
    __nv_bfloat16 hxx, hyy, hzz, hww, lx, ly, lz, lw;
    hilo(rx, hxx, lx); hilo(ry, hyy, ly);
    hilo(rz, hzz, lz); hilo(rw, hww, lw);
    size_t o = (size_t)w * KK + D + lane * 4;
    *(__nv_bfloat162*)(g_Ah + o)     = __nv_bfloat162(hxx, hyy);
    *(__nv_bfloat162*)(g_Ah + o + 2) = __nv_bfloat162(hzz, hww);
    *(__nv_bfloat162*)(g_Al + o)     = __nv_bfloat162(lx, ly);
    *(__nv_bfloat162*)(g_Al + o + 2) = __nv_bfloat162(lz, lw);
}

// ================= bf16x3 HMMA GEMM, cp.async 3-stage pipeline =================
#define STAGE_SZ 32768
#define T_AL 8192
#define T_BH 16384
#define T_BL 24576

extern __shared__ __align__(16) uint8_t dynsm[];

// mode: 0 = intermediate layer (write bf16 hi/lo + fp16 table, relu)
//       1 = final layer (write fp32 d_out, no relu)
__global__ void __launch_bounds__(256, 2) k_gemm(
    float* __restrict__ out, const float* __restrict__ bias,
    int layer, int final_layer)
{
    const int t    = threadIdx.x;
    const int warp = t >> 5;
    const int lane = t & 31;
    const int warpRow = (warp >> 1) * 32;
    const int warpCol = (warp & 1) * 64;
    const long rowBase = (long)blockIdx.x * 128;

    const uint32_t sbase = smem_u32(dynsm);
    const int jq = lane >> 3;
    const int rr = lane & 7;

    const __nv_bfloat16* gW_h = g_Wh + (size_t)layer * D * KK;
    const __nv_bfloat16* gW_l = g_Wl + (size_t)layer * D * KK;

    const int r0s = (t + 0)   >> 2, c0s = (t + 0)   & 3;
    const int r1s = (t + 256) >> 2, c1s = (t + 256) & 3;

    float acc[2][8][4];
#pragma unroll
    for (int i = 0; i < 2; i++)
#pragma unroll
        for (int j = 0; j < 8; j++)
#pragma unroll
            for (int q = 0; q < 4; q++) acc[i][j][q] = 0.f;

    auto issue = [&](int kc, int stage) {
        const uint32_t base = sbase + stage * STAGE_SZ;
        const int koff = kc * 32;
#pragma unroll
        for (int i = 0; i < 2; i++) {
            const int r = i ? r1s : r0s;
            const int c = i ? c1s : c0s;
            long row = rowBase + r;
            uint32_t sz = (row < NN) ? 16u : 0u;
            long arow = (row < NN) ? row : 0;
            const void* pAh = g_Ah + arow * KK + koff + c * 8;
            const void* pAl = g_Al + arow * KK + koff + c * 8;
            const void* pBh = gW_h + (size_t)r * KK + koff + c * 8;
            const void* pBl = gW_l + (size_t)r * KK + koff + c * 8;
            uint32_t o = swz(r, c);
            CP_ASYNC(base + o,        pAh, sz);
            CP_ASYNC(base + o + T_AL, pAl, sz);
            CP_ASYNC(base + o + T_BH, pBh, 16u);
            CP_ASYNC(base + o + T_BL, pBl, 16u);
        }
        CP_COMMIT();
    };

    issue(0, 0);

    for (int kc = 0; kc < 8; kc++) {
        const int stage = kc % 3;
        if (kc < 7) issue(kc + 1, (kc + 1) % 3);
        if (kc < 7) { CP_WAIT1(); } else { CP_WAIT0(); }
        __syncthreads();

        const uint32_t base = sbase + stage * STAGE_SZ;
#pragma unroll
        for (int ks = 0; ks < 2; ks++) {
            uint32_t ah[2][4], al[2][4];
#pragma unroll
            for (int ma = 0; ma < 2; ma++) {
                int ra = warpRow + ma * 16 + (jq & 1) * 8 + rr;
                int ca = ks * 2 + (jq >> 1);
                uint32_t off = swz(ra, ca);
                LDSM4(ah[ma][0], ah[ma][1], ah[ma][2], ah[ma][3], base + off);
                LDSM4(al[ma][0], al[ma][1], al[ma][2], al[ma][3], base + off + T_AL);
            }
#pragma unroll
            for (int g = 0; g < 4; g++) {
                int rb = warpCol + g * 16 + (jq >> 1) * 8 + rr;
                int cb = ks * 2 + (jq & 1);
                uint32_t boff = swz(rb, cb);
                uint32_t bh[4], bl[4];
                LDSM4(bh[0], bh[1], bh[2], bh[3], base + boff + T_BH);
                LDSM4(bl[0], bl[1], bl[2], bl[3], base + boff + T_BL);
#pragma unroll
                for (int sub = 0; sub < 2; sub++) {
                    int na = g * 2 + sub;
                    uint32_t b0h = bh[sub * 2], b1h = bh[sub * 2 + 1];
                    uint32_t b0l = bl[sub * 2], b1l = bl[sub * 2 + 1];
#pragma unroll
                    for (int ma = 0; ma < 2; ma++) {
                        mma_bf16(acc[ma][na], ah[ma], b0h, b1h);
                        mma_bf16(acc[ma][na], ah[ma], b0l, b1l);
                        mma_bf16(acc[ma][na], al[ma], b0h, b1h);
                    }
                }
            }
        }
        __syncthreads();
    }

    const float* bl = bias + (size_t)layer * D;
    const int q2 = (lane & 3) * 2;
    const int rq = lane >> 2;
#pragma unroll
    for (int na = 0; na < 8; na++) {
        int col = warpCol + na * 8 + q2;
        float2 bv = *(const float2*)(bl + col);
#pragma unroll
        for (int ma = 0; ma < 2; ma++) {
            float* c = acc[ma][na];
            long r0 = rowBase + warpRow + ma * 16 + rq;
#pragma unroll
            for (int h = 0; h < 2; h++) {
                long row = r0 + h * 8;
                if (row >= NN) continue;
                float ox = c[h * 2 + 0] + bv.x;
                float oy = c[h * 2 + 1] + bv.y;
                if (final_layer) {
                    *(float2*)(out + row * D + col) = make_float2(ox, oy);
                } else {
                    ox = fmaxf(ox, 0.f);
                    oy = fmaxf(oy, 0.f);
                    __nv_bfloat16 hx, hy, lx, ly;
                    hilo(ox, hx, lx);
                    hilo(oy, hy, ly);
                    size_t o = (size_t)row * KK + col;
                    *(__nv_bfloat162*)(g_Ah + o) = __nv_bfloat162(hx, hy);
                    *(__nv_bfloat162*)(g_Al + o) = __nv_bfloat162(lx, ly);
                    *(__half2*)(g_hx + (size_t)row * D + col) =
                        __floats2half2_rn(ox, oy);
                }
            }
        }
    }
}

// ---------------------------------------------------------------
extern "C" void kernel_launch(void* const* d_in, const int* in_sizes, int n_in,
                              void* d_out, int out_size) {
    const float* emb = (const float*)d_in[0];
    const float* Ws  = (const float*)d_in[1];
    const float* Wn  = (const float*)d_in[2];
    const float* b   = (const float*)d_in[3];
    const int*   src = (const int*)d_in[4];
    const int*   dst = (const int*)d_in[5];
    float*       out = (float*)d_out;

    void* pdeg;
    cudaGetSymbolAddress(&pdeg, g_deg);

    cudaFuncSetAttribute(k_gemm, cudaFuncAttributeMaxDynamicSharedMemorySize,
                         3 * STAGE_SZ);

    // one-time conversions + CSR build
    k_cvtw<<<(3 * KK * D + 255) / 256, 256>>>(Ws, Wn);
    k_cvtx<<<(NN * 32 + 255) / 256, 256>>>((const float4*)emb);
    cudaMemsetAsync(pdeg, 0, NN * sizeof(int));
    k_count<<<(NE + 255) / 256, 256>>>(dst);
    k_part<<<SCAN_NB, 256>>>();
    k_scanp<<<1, 512>>>();
    k_write<<<SCAN_NB, 256>>>();
    k_fill<<<(NE + 255) / 256, 256>>>(src, dst);

    const int aggGrid  = (NN + 7) / 8;
    const int gemmGrid = (NN + 127) / 128;

    k_agg<<<aggGrid, 256>>>();
    k_gemm<<<gemmGrid, 256, 3 * STAGE_SZ>>>(out, b, 0, 0);

    k_agg<<<aggGrid, 256>>>();
    k_gemm<<<gemmGrid, 256, 3 * STAGE_SZ>>>(out, b, 1, 0);

    k_agg<<<aggGrid, 256>>>();
    k_gemm<<<gemmGrid, 256, 3 * STAGE_SZ>>>(out, b, 2, 1);
}

// round 8
// speedup vs baseline: 3.6688x; 1.3656x over previous
#include <cuda_runtime.h>
#include <cuda_bf16.h>
#include <cuda_fp16.h>
#include <cstdint>

#define NN 100000
#define NE 1600000
#define D  128
#define KK 256   // concat(x, neigh)

#define SCAN_NB ((NN + 255) / 256)   // 391

// ---- scratch (static device globals; no runtime allocation) ----
__device__ int   g_deg[NN];
__device__ float g_inv[NN];
__device__ int   g_rowptr[NN + 1];
__device__ int   g_cursor[NN];
__device__ int   g_esrc[NE];
__device__ int   g_part[SCAN_NB];
__device__ int   g_pscan[SCAN_NB];
__device__ __half g_hx[(size_t)NN * KK];   // fp16 A operand: cols 0-127 x, 128-255 neigh
__device__ __half g_Wh[3 * D * KK];        // W^T concat fp16 hi, [layer][n][k]
__device__ __half g_Wl[3 * D * KK];        // fp16 lo (residual)

// ================= helpers =================
__device__ __forceinline__ uint32_t smem_u32(const void* p) {
    uint32_t a;
    asm("{ .reg .u64 t; cvta.to.shared.u64 t, %1; cvt.u32.u64 %0, t; }"
        : "=r"(a) : "l"(p));
    return a;
}
#define LDSM4(d0, d1, d2, d3, addr)                                         \
    asm volatile("ldmatrix.sync.aligned.m8n8.x4.shared.b16 {%0,%1,%2,%3}, [%4];" \
                 : "=r"(d0), "=r"(d1), "=r"(d2), "=r"(d3) : "r"(addr))

__device__ __forceinline__ void mma_f16(float* c, const uint32_t* a,
                                        uint32_t b0, uint32_t b1) {
    asm volatile(
        "mma.sync.aligned.m16n8k16.row.col.f32.f16.f16.f32 "
        "{%0,%1,%2,%3}, {%4,%5,%6,%7}, {%8,%9}, {%0,%1,%2,%3};\n"
        : "+f"(c[0]), "+f"(c[1]), "+f"(c[2]), "+f"(c[3])
        : "r"(a[0]), "r"(a[1]), "r"(a[2]), "r"(a[3]), "r"(b0), "r"(b1));
}

#define CP_ASYNC(dst, src, sz)                                              \
    asm volatile("cp.async.cg.shared.global [%0], [%1], 16, %2;"            \
                 :: "r"(dst), "l"(src), "r"(sz))
#define CP_COMMIT() asm volatile("cp.async.commit_group;" ::: "memory")
#define CP_WAIT1()  asm volatile("cp.async.wait_group 1;" ::: "memory")
#define CP_WAIT0()  asm volatile("cp.async.wait_group 0;" ::: "memory")

__device__ __forceinline__ uint32_t swz(int r, int c) {
    return (uint32_t)(r * 64 + ((c ^ ((r >> 1) & 3)) << 4));
}

// ================= one-time conversions =================
// W concat transpose -> fp16 hi/lo: [layer][n][k], k 0..127 self, 128..255 neigh
__global__ void k_cvtw(const float* __restrict__ Ws, const float* __restrict__ Wn) {
    int id = blockIdx.x * blockDim.x + threadIdx.x;
    if (id >= 3 * KK * D) return;
    int n = id & (D - 1);
    int k = (id >> 7) & (KK - 1);
    int l = id >> 15;
    float v = (k < D) ? Ws[(l * D + k) * D + n] : Wn[(l * D + (k - D)) * D + n];
    __half h = __float2half_rn(v);
    __half lo = __float2half_rn(v - __half2float(h));
    int o = (l * D + n) * KK + k;
    g_Wh[o] = h;
    g_Wl[o] = lo;
}

// emb fp32 -> g_hx cols 0..127 (fp16)
__global__ void k_cvtx(const float4* __restrict__ x4) {
    int id = blockIdx.x * blockDim.x + threadIdx.x;
    if (id >= NN * 32) return;
    int row = id >> 5, j = id & 31;
    float4 v = x4[id];
    __half2* ph = (__half2*)(g_hx + (size_t)row * KK + j * 4);
    ph[0] = __floats2half2_rn(v.x, v.y);
    ph[1] = __floats2half2_rn(v.z, v.w);
}

// ================= CSR build =================
__global__ void k_count(const int* __restrict__ dst) {
    int e = blockIdx.x * blockDim.x + threadIdx.x;
    if (e < NE) atomicAdd(&g_deg[dst[e]], 1);
}

__global__ void k_part() {
    int i = blockIdx.x * 256 + threadIdx.x;
    int lane = threadIdx.x & 31, warp = threadIdx.x >> 5;
    int v = (i < NN) ? g_deg[i] : 0;
#pragma unroll
    for (int off = 16; off > 0; off >>= 1)
        v += __shfl_down_sync(0xFFFFFFFFu, v, off);
    __shared__ int ws[8];
    if (lane == 0) ws[warp] = v;
    __syncthreads();
    if (threadIdx.x < 8) {
        int s = ws[threadIdx.x];
#pragma unroll
        for (int off = 4; off > 0; off >>= 1)
            s += __shfl_down_sync(0xFFu, s, off);
        if (threadIdx.x == 0) g_part[blockIdx.x] = s;
    }
}

__global__ void k_scanp() {
    __shared__ int sp[512];
    int t = threadIdx.x;
    sp[t] = (t < SCAN_NB) ? g_part[t] : 0;
    __syncthreads();
#pragma unroll
    for (int off = 1; off < 512; off <<= 1) {
        int v = (t >= off) ? sp[t - off] : 0;
        __syncthreads();
        sp[t] += v;
        __syncthreads();
    }
    if (t < SCAN_NB) g_pscan[t] = (t == 0) ? 0 : sp[t - 1];
}

__global__ void k_write() {
    int i = blockIdx.x * 256 + threadIdx.x;
    int lane = threadIdx.x & 31, warp = threadIdx.x >> 5;
    int d = (i < NN) ? g_deg[i] : 0;
    int x = d;
#pragma unroll
    for (int off = 1; off < 32; off <<= 1) {
        int y = __shfl_up_sync(0xFFFFFFFFu, x, off);
        if (lane >= off) x += y;
    }
    __shared__ int ws[8];
    if (lane == 31) ws[warp] = x;
    __syncthreads();
    if (warp == 0 && lane < 8) {
        int s = ws[lane];
#pragma unroll
        for (int off = 1; off < 8; off <<= 1) {
            int y = __shfl_up_sync(0xFFu, s, off);
            if (lane >= off) s += y;
        }
        ws[lane] = s;
    }
    __syncthreads();
    int base = g_pscan[blockIdx.x] + ((warp == 0) ? 0 : ws[warp - 1]);
    int excl = base + x - d;
    if (i < NN) {
        g_rowptr[i] = excl;
        g_cursor[i] = excl;
        g_inv[i]    = 1.0f / (float)max(d, 1);
        if (i == NN - 1) g_rowptr[NN] = excl + d;
    }
}

__global__ void k_fill(const int* __restrict__ src, const int* __restrict__ dst) {
    int e = blockIdx.x * blockDim.x + threadIdx.x;
    if (e < NE) {
        int p = atomicAdd(&g_cursor[dst[e]], 1);
        g_esrc[p] = src[e];
    }
}

// ================= aggregation: fp16 gather, fp32 acc, fp16 neigh write ====
__global__ void k_agg() {
    int w    = (blockIdx.x * blockDim.x + threadIdx.x) >> 5;
    int lane = threadIdx.x & 31;
    if (w >= NN) return;
    int beg = g_rowptr[w];
    int end = g_rowptr[w + 1];
    float4 a0 = make_float4(0.f, 0.f, 0.f, 0.f);
    float4 a1 = make_float4(0.f, 0.f, 0.f, 0.f);
    float4 a2 = make_float4(0.f, 0.f, 0.f, 0.f);
    float4 a3 = make_float4(0.f, 0.f, 0.f, 0.f);
    const uint2* hx = (const uint2*)g_hx;   // row = 64 uint2 (256 halfs); x = first 32
    int e = beg;
    for (; e + 3 < end; e += 4) {
        int s0 = g_esrc[e], s1 = g_esrc[e + 1], s2 = g_esrc[e + 2], s3 = g_esrc[e + 3];
        uint2 u0 = __ldg(hx + (long)s0 * 64 + lane);
        uint2 u1 = __ldg(hx + (long)s1 * 64 + lane);
        uint2 u2 = __ldg(hx + (long)s2 * 64 + lane);
        uint2 u3 = __ldg(hx + (long)s3 * 64 + lane);
        float2 p, q;
        p = __half22float2(*(__half2*)&u0.x); q = __half22float2(*(__half2*)&u0.y);
        a0.x += p.x; a0.y += p.y; a0.z += q.x; a0.w += q.y;
        p = __half22float2(*(__half2*)&u1.x); q = __half22float2(*(__half2*)&u1.y);
        a1.x += p.x; a1.y += p.y; a1.z += q.x; a1.w += q.y;
        p = __half22float2(*(__half2*)&u2.x); q = __half22float2(*(__half2*)&u2.y);
        a2.x += p.x; a2.y += p.y; a2.z += q.x; a2.w += q.y;
        p = __half22float2(*(__half2*)&u3.x); q = __half22float2(*(__half2*)&u3.y);
        a3.x += p.x; a3.y += p.y; a3.z += q.x; a3.w += q.y;
    }
    for (; e < end; e++) {
        int s0 = g_esrc[e];
        uint2 u0 = __ldg(hx + (long)s0 * 64 + lane);
        float2 p = __half22float2(*(__half2*)&u0.x);
        float2 q = __half22float2(*(__half2*)&u0.y);
        a0.x += p.x; a0.y += p.y; a0.z += q.x; a0.w += q.y;
    }
    float iv = g_inv[w];
    float rx = (a0.x + a1.x + a2.x + a3.x) * iv;
    float ry = (a0.y + a1.y + a2.y + a3.y) * iv;
    float rz = (a0.z + a1.z + a2.z + a3.z) * iv;
    float rw = (a0.w + a1.w + a2.w + a3.w) * iv;
    __half2* pn = (__half2*)(g_hx + (size_t)w * KK + D + lane * 4);
    pn[0] = __floats2half2_rn(rx, ry);
    pn[1] = __floats2half2_rn(rz, rw);
}

// ================= fp16 HMMA GEMM (W in fp16 hi/lo), cp.async 3-stage =========
// block 128x128 out; 8 warps, warp 32x64; K=256 / 8 chunks of 32.
// stage = [A 8K | Wh 8K | Wl 8K] = 24KB; acc += a*whi + a*wlo.
#define STAGE_SZ 24576
#define T_WH 8192
#define T_WL 16384

extern __shared__ __align__(16) uint8_t dynsm[];

__global__ void __launch_bounds__(256, 2) k_gemm(
    float* __restrict__ out, const float* __restrict__ bias,
    int layer, int final_layer)
{
    const int t    = threadIdx.x;
    const int warp = t >> 5;
    const int lane = t & 31;
    const int warpRow = (warp >> 1) * 32;
    const int warpCol = (warp & 1) * 64;
    const long rowBase = (long)blockIdx.x * 128;

    const uint32_t sbase = smem_u32(dynsm);
    const int jq = lane >> 3;
    const int rr = lane & 7;

    const __half* gW_h = g_Wh + (size_t)layer * D * KK;
    const __half* gW_l = g_Wl + (size_t)layer * D * KK;

    const int r0s = (t + 0)   >> 2, c0s = (t + 0)   & 3;
    const int r1s = (t + 256) >> 2, c1s = (t + 256) & 3;

    float acc[2][8][4];
#pragma unroll
    for (int i = 0; i < 2; i++)
#pragma unroll
        for (int j = 0; j < 8; j++)
#pragma unroll
            for (int q = 0; q < 4; q++) acc[i][j][q] = 0.f;

    auto issue = [&](int kc, int stage) {
        const uint32_t base = sbase + stage * STAGE_SZ;
        const int koff = kc * 32;
#pragma unroll
        for (int i = 0; i < 2; i++) {
            const int r = i ? r1s : r0s;
            const int c = i ? c1s : c0s;
            long row = rowBase + r;
            uint32_t sz = (row < NN) ? 16u : 0u;
            long arow = (row < NN) ? row : 0;
            const void* pA  = g_hx + arow * KK + koff + c * 8;
            const void* pWh = gW_h + (size_t)r * KK + koff + c * 8;
            const void* pWl = gW_l + (size_t)r * KK + koff + c * 8;
            uint32_t o = swz(r, c);
            CP_ASYNC(base + o,        pA,  sz);
            CP_ASYNC(base + o + T_WH, pWh, 16u);
            CP_ASYNC(base + o + T_WL, pWl, 16u);
        }
        CP_COMMIT();
    };

    issue(0, 0);

    for (int kc = 0; kc < 8; kc++) {
        const int stage = kc % 3;
        if (kc < 7) issue(kc + 1, (kc + 1) % 3);
        if (kc < 7) { CP_WAIT1(); } else { CP_WAIT0(); }
        __syncthreads();

        const uint32_t base = sbase + stage * STAGE_SZ;
#pragma unroll
        for (int ks = 0; ks < 2; ks++) {
            uint32_t af[2][4];
#pragma unroll
            for (int ma = 0; ma < 2; ma++) {
                int ra = warpRow + ma * 16 + (jq & 1) * 8 + rr;
                int ca = ks * 2 + (jq >> 1);
                LDSM4(af[ma][0], af[ma][1], af[ma][2], af[ma][3], base + swz(ra, ca));
            }
#pragma unroll
            for (int g = 0; g < 4; g++) {
                int rb = warpCol + g * 16 + (jq >> 1) * 8 + rr;
                int cb = ks * 2 + (jq & 1);
                uint32_t boff = swz(rb, cb);
                uint32_t bh[4], bl[4];
                LDSM4(bh[0], bh[1], bh[2], bh[3], base + boff + T_WH);
                LDSM4(bl[0], bl[1], bl[2], bl[3], base + boff + T_WL);
#pragma unroll
                for (int sub = 0; sub < 2; sub++) {
                    int na = g * 2 + sub;
                    uint32_t b0h = bh[sub * 2], b1h = bh[sub * 2 + 1];
                    uint32_t b0l = bl[sub * 2], b1l = bl[sub * 2 + 1];
#pragma unroll
                    for (int ma = 0; ma < 2; ma++) {
                        mma_f16(acc[ma][na], af[ma], b0h, b1h);
                        mma_f16(acc[ma][na], af[ma], b0l, b1l);
                    }
                }
            }
        }
        __syncthreads();
    }

    const float* bl = bias + (size_t)layer * D;
    const int q2 = (lane & 3) * 2;
    const int rq = lane >> 2;
#pragma unroll
    for (int na = 0; na < 8; na++) {
        int col = warpCol + na * 8 + q2;
        float2 bv = *(const float2*)(bl + col);
#pragma unroll
        for (int ma = 0; ma < 2; ma++) {
            float* c = acc[ma][na];
            long r0 = rowBase + warpRow + ma * 16 + rq;
#pragma unroll
            for (int h = 0; h < 2; h++) {
                long row = r0 + h * 8;
                if (row >= NN) continue;
                float ox = c[h * 2 + 0] + bv.x;
                float oy = c[h * 2 + 1] + bv.y;
                if (final_layer) {
                    *(float2*)(out + row * D + col) = make_float2(ox, oy);
                } else {
                    ox = fmaxf(ox, 0.f);
                    oy = fmaxf(oy, 0.f);
                    *(__half2*)(g_hx + (size_t)row * KK + col) =
                        __floats2half2_rn(ox, oy);
                }
            }
        }
    }
}

// ---------------------------------------------------------------
extern "C" void kernel_launch(void* const* d_in, const int* in_sizes, int n_in,
                              void* d_out, int out_size) {
    const float* emb = (const float*)d_in[0];
    const float* Ws  = (const float*)d_in[1];
    const float* Wn  = (const float*)d_in[2];
    const float* b   = (const float*)d_in[3];
    const int*   src = (const int*)d_in[4];
    const int*   dst = (const int*)d_in[5];
    float*       out = (float*)d_out;

    void* pdeg;
    cudaGetSymbolAddress(&pdeg, g_deg);

    cudaFuncSetAttribute(k_gemm, cudaFuncAttributeMaxDynamicSharedMemorySize,
                         3 * STAGE_SZ);

    // one-time conversions + CSR build
    k_cvtw<<<(3 * KK * D + 255) / 256, 256>>>(Ws, Wn);
    k_cvtx<<<(NN * 32 + 255) / 256, 256>>>((const float4*)emb);
    cudaMemsetAsync(pdeg, 0, NN * sizeof(int));
    k_count<<<(NE + 255) / 256, 256>>>(dst);
    k_part<<<SCAN_NB, 256>>>();
    k_scanp<<<1, 512>>>();
    k_write<<<SCAN_NB, 256>>>();
    k_fill<<<(NE + 255) / 256, 256>>>(src, dst);

    const int aggGrid  = (NN + 7) / 8;
    const int gemmGrid = (NN + 127) / 128;

    k_agg<<<aggGrid, 256>>>();
    k_gemm<<<gemmGrid, 256, 3 * STAGE_SZ>>>(out, b, 0, 0);

    k_agg<<<aggGrid, 256>>>();
    k_gemm<<<gemmGrid, 256, 3 * STAGE_SZ>>>(out, b, 1, 0);

    k_agg<<<aggGrid, 256>>>();
    k_gemm<<<gemmGrid, 256, 3 * STAGE_SZ>>>(out, b, 2, 1);
}

// round 9
// speedup vs baseline: 4.2195x; 1.1501x over previous
#include <cuda_runtime.h>
#include <cuda_bf16.h>
#include <cuda_fp16.h>
#include <cstdint>

#define NN 100000
#define NE 1600000
#define D  128
#define KK 256   // concat(x, neigh)

#define SCAN_NB ((NN + 255) / 256)   // 391

// ---- scratch (static device globals; no runtime allocation) ----
__device__ int   g_deg[NN];
__device__ float g_inv[NN];
__device__ int   g_rowptr[NN + 1];
__device__ int   g_cursor[NN];
__device__ int   g_esrc[NE];
__device__ int   g_part[SCAN_NB];
__device__ int   g_pscan[SCAN_NB];
__device__ __half g_hx[(size_t)NN * KK];   // fp16 A operand: cols 0-127 x, 128-255 neigh
__device__ __half g_Wh[3 * D * KK];        // W^T concat fp16, [layer][n][k]

// ================= helpers =================
__device__ __forceinline__ uint32_t smem_u32(const void* p) {
    uint32_t a;
    asm("{ .reg .u64 t; cvta.to.shared.u64 t, %1; cvt.u32.u64 %0, t; }"
        : "=r"(a) : "l"(p));
    return a;
}
#define LDSM4(d0, d1, d2, d3, addr)                                         \
    asm volatile("ldmatrix.sync.aligned.m8n8.x4.shared.b16 {%0,%1,%2,%3}, [%4];" \
                 : "=r"(d0), "=r"(d1), "=r"(d2), "=r"(d3) : "r"(addr))

__device__ __forceinline__ void mma_f16(float* c, const uint32_t* a,
                                        uint32_t b0, uint32_t b1) {
    asm volatile(
        "mma.sync.aligned.m16n8k16.row.col.f32.f16.f16.f32 "
        "{%0,%1,%2,%3}, {%4,%5,%6,%7}, {%8,%9}, {%0,%1,%2,%3};\n"
        : "+f"(c[0]), "+f"(c[1]), "+f"(c[2]), "+f"(c[3])
        : "r"(a[0]), "r"(a[1]), "r"(a[2]), "r"(a[3]), "r"(b0), "r"(b1));
}

#define CP_ASYNC(dst, src, sz)                                              \
    asm volatile("cp.async.cg.shared.global [%0], [%1], 16, %2;"            \
                 :: "r"(dst), "l"(src), "r"(sz))
#define CP_COMMIT() asm volatile("cp.async.commit_group;" ::: "memory")
#define CP_WAIT1()  asm volatile("cp.async.wait_group 1;" ::: "memory")
#define CP_WAIT0()  asm volatile("cp.async.wait_group 0;" ::: "memory")

__device__ __forceinline__ uint32_t swz(int r, int c) {
    return (uint32_t)(r * 64 + ((c ^ ((r >> 1) & 3)) << 4));
}

// ================= one-time conversions =================
// W concat transpose -> fp16: [layer][n][k], k 0..127 self, 128..255 neigh
__global__ void k_cvtw(const float* __restrict__ Ws, const float* __restrict__ Wn) {
    int id = blockIdx.x * blockDim.x + threadIdx.x;
    if (id >= 3 * KK * D) return;
    int n = id & (D - 1);
    int k = (id >> 7) & (KK - 1);
    int l = id >> 15;
    float v = (k < D) ? Ws[(l * D + k) * D + n] : Wn[(l * D + (k - D)) * D + n];
    g_Wh[(l * D + n) * KK + k] = __float2half_rn(v);
}

// emb fp32 -> g_hx cols 0..127 (fp16)
__global__ void k_cvtx(const float4* __restrict__ x4) {
    int id = blockIdx.x * blockDim.x + threadIdx.x;
    if (id >= NN * 32) return;
    int row = id >> 5, j = id & 31;
    float4 v = x4[id];
    __half2* ph = (__half2*)(g_hx + (size_t)row * KK + j * 4);
    ph[0] = __floats2half2_rn(v.x, v.y);
    ph[1] = __floats2half2_rn(v.z, v.w);
}

// ================= CSR build =================
__global__ void k_count(const int* __restrict__ dst) {
    int e = blockIdx.x * blockDim.x + threadIdx.x;
    if (e < NE) atomicAdd(&g_deg[dst[e]], 1);
}

__global__ void k_part() {
    int i = blockIdx.x * 256 + threadIdx.x;
    int lane = threadIdx.x & 31, warp = threadIdx.x >> 5;
    int v = (i < NN) ? g_deg[i] : 0;
#pragma unroll
    for (int off = 16; off > 0; off >>= 1)
        v += __shfl_down_sync(0xFFFFFFFFu, v, off);
    __shared__ int ws[8];
    if (lane == 0) ws[warp] = v;
    __syncthreads();
    if (threadIdx.x < 8) {
        int s = ws[threadIdx.x];
#pragma unroll
        for (int off = 4; off > 0; off >>= 1)
            s += __shfl_down_sync(0xFFu, s, off);
        if (threadIdx.x == 0) g_part[blockIdx.x] = s;
    }
}

__global__ void k_scanp() {
    __shared__ int sp[512];
    int t = threadIdx.x;
    sp[t] = (t < SCAN_NB) ? g_part[t] : 0;
    __syncthreads();
#pragma unroll
    for (int off = 1; off < 512; off <<= 1) {
        int v = (t >= off) ? sp[t - off] : 0;
        __syncthreads();
        sp[t] += v;
        __syncthreads();
    }
    if (t < SCAN_NB) g_pscan[t] = (t == 0) ? 0 : sp[t - 1];
}

__global__ void k_write() {
    int i = blockIdx.x * 256 + threadIdx.x;
    int lane = threadIdx.x & 31, warp = threadIdx.x >> 5;
    int d = (i < NN) ? g_deg[i] : 0;
    int x = d;
#pragma unroll
    for (int off = 1; off < 32; off <<= 1) {
        int y = __shfl_up_sync(0xFFFFFFFFu, x, off);
        if (lane >= off) x += y;
    }
    __shared__ int ws[8];
    if (lane == 31) ws[warp] = x;
    __syncthreads();
    if (warp == 0 && lane < 8) {
        int s = ws[lane];
#pragma unroll
        for (int off = 1; off < 8; off <<= 1) {
            int y = __shfl_up_sync(0xFFu, s, off);
            if (lane >= off) s += y;
        }
        ws[lane] = s;
    }
    __syncthreads();
    int base = g_pscan[blockIdx.x] + ((warp == 0) ? 0 : ws[warp - 1]);
    int excl = base + x - d;
    if (i < NN) {
        g_rowptr[i] = excl;
        g_cursor[i] = excl;
        g_inv[i]    = 1.0f / (float)max(d, 1);
        if (i == NN - 1) g_rowptr[NN] = excl + d;
    }
}

__global__ void k_fill(const int* __restrict__ src, const int* __restrict__ dst) {
    int e = blockIdx.x * blockDim.x + threadIdx.x;
    if (e < NE) {
        int p = atomicAdd(&g_cursor[dst[e]], 1);
        g_esrc[p] = src[e];
    }
}

// ================= aggregation: fp16 gather, fp32 acc, fp16 neigh write ====
__global__ void k_agg() {
    int w    = (blockIdx.x * blockDim.x + threadIdx.x) >> 5;
    int lane = threadIdx.x & 31;
    if (w >= NN) return;
    int beg = g_rowptr[w];
    int end = g_rowptr[w + 1];
    float4 a0 = make_float4(0.f, 0.f, 0.f, 0.f);
    float4 a1 = make_float4(0.f, 0.f, 0.f, 0.f);
    float4 a2 = make_float4(0.f, 0.f, 0.f, 0.f);
    float4 a3 = make_float4(0.f, 0.f, 0.f, 0.f);
    const uint2* hx = (const uint2*)g_hx;   // row = 64 uint2 (256 halfs); x = first 32
    int e = beg;
    for (; e + 3 < end; e += 4) {
        int s0 = g_esrc[e], s1 = g_esrc[e + 1], s2 = g_esrc[e + 2], s3 = g_esrc[e + 3];
        uint2 u0 = __ldg(hx + (long)s0 * 64 + lane);
        uint2 u1 = __ldg(hx + (long)s1 * 64 + lane);
        uint2 u2 = __ldg(hx + (long)s2 * 64 + lane);
        uint2 u3 = __ldg(hx + (long)s3 * 64 + lane);
        float2 p, q;
        p = __half22float2(*(__half2*)&u0.x); q = __half22float2(*(__half2*)&u0.y);
        a0.x += p.x; a0.y += p.y; a0.z += q.x; a0.w += q.y;
        p = __half22float2(*(__half2*)&u1.x); q = __half22float2(*(__half2*)&u1.y);
        a1.x += p.x; a1.y += p.y; a1.z += q.x; a1.w += q.y;
        p = __half22float2(*(__half2*)&u2.x); q = __half22float2(*(__half2*)&u2.y);
        a2.x += p.x; a2.y += p.y; a2.z += q.x; a2.w += q.y;
        p = __half22float2(*(__half2*)&u3.x); q = __half22float2(*(__half2*)&u3.y);
        a3.x += p.x; a3.y += p.y; a3.z += q.x; a3.w += q.y;
    }
    for (; e < end; e++) {
        int s0 = g_esrc[e];
        uint2 u0 = __ldg(hx + (long)s0 * 64 + lane);
        float2 p = __half22float2(*(__half2*)&u0.x);
        float2 q = __half22float2(*(__half2*)&u0.y);
        a0.x += p.x; a0.y += p.y; a0.z += q.x; a0.w += q.y;
    }
    float iv = g_inv[w];
    float rx = (a0.x + a1.x + a2.x + a3.x) * iv;
    float ry = (a0.y + a1.y + a2.y + a3.y) * iv;
    float rz = (a0.z + a1.z + a2.z + a3.z) * iv;
    float rw = (a0.w + a1.w + a2.w + a3.w) * iv;
    __half2* pn = (__half2*)(g_hx + (size_t)w * KK + D + lane * 4);
    pn[0] = __floats2half2_rn(rx, ry);
    pn[1] = __floats2half2_rn(rz, rw);
}

// ================= fp16 HMMA GEMM (single term), cp.async 3-stage =========
// block 128x128 out; 8 warps, warp 32x64; K=256 / 8 chunks of 32.
// stage = [A 8K | W 8K] = 16KB; acc += a*w.
#define STAGE_SZ 16384
#define T_WH 8192

extern __shared__ __align__(16) uint8_t dynsm[];

__global__ void __launch_bounds__(256, 2) k_gemm(
    float* __restrict__ out, const float* __restrict__ bias,
    int layer, int final_layer)
{
    const int t    = threadIdx.x;
    const int warp = t >> 5;
    const int lane = t & 31;
    const int warpRow = (warp >> 1) * 32;
    const int warpCol = (warp & 1) * 64;
    const long rowBase = (long)blockIdx.x * 128;

    const uint32_t sbase = smem_u32(dynsm);
    const int jq = lane >> 3;
    const int rr = lane & 7;

    const __half* gW_h = g_Wh + (size_t)layer * D * KK;

    const int r0s = (t + 0)   >> 2, c0s = (t + 0)   & 3;
    const int r1s = (t + 256) >> 2, c1s = (t + 256) & 3;

    float acc[2][8][4];
#pragma unroll
    for (int i = 0; i < 2; i++)
#pragma unroll
        for (int j = 0; j < 8; j++)
#pragma unroll
            for (int q = 0; q < 4; q++) acc[i][j][q] = 0.f;

    auto issue = [&](int kc, int stage) {
        const uint32_t base = sbase + stage * STAGE_SZ;
        const int koff = kc * 32;
#pragma unroll
        for (int i = 0; i < 2; i++) {
            const int r = i ? r1s : r0s;
            const int c = i ? c1s : c0s;
            long row = rowBase + r;
            uint32_t sz = (row < NN) ? 16u : 0u;
            long arow = (row < NN) ? row : 0;
            const void* pA  = g_hx + arow * KK + koff + c * 8;
            const void* pWh = gW_h + (size_t)r * KK + koff + c * 8;
            uint32_t o = swz(r, c);
            CP_ASYNC(base + o,        pA,  sz);
            CP_ASYNC(base + o + T_WH, pWh, 16u);
        }
        CP_COMMIT();
    };

    issue(0, 0);

    for (int kc = 0; kc < 8; kc++) {
        const int stage = kc % 3;
        if (kc < 7) issue(kc + 1, (kc + 1) % 3);
        if (kc < 7) { CP_WAIT1(); } else { CP_WAIT0(); }
        __syncthreads();

        const uint32_t base = sbase + stage * STAGE_SZ;
#pragma unroll
        for (int ks = 0; ks < 2; ks++) {
            uint32_t af[2][4];
#pragma unroll
            for (int ma = 0; ma < 2; ma++) {
                int ra = warpRow + ma * 16 + (jq & 1) * 8 + rr;
                int ca = ks * 2 + (jq >> 1);
                LDSM4(af[ma][0], af[ma][1], af[ma][2], af[ma][3], base + swz(ra, ca));
            }
#pragma unroll
            for (int g = 0; g < 4; g++) {
                int rb = warpCol + g * 16 + (jq >> 1) * 8 + rr;
                int cb = ks * 2 + (jq & 1);
                uint32_t bh[4];
                LDSM4(bh[0], bh[1], bh[2], bh[3], base + swz(rb, cb) + T_WH);
#pragma unroll
                for (int sub = 0; sub < 2; sub++) {
                    int na = g * 2 + sub;
                    uint32_t b0h = bh[sub * 2], b1h = bh[sub * 2 + 1];
#pragma unroll
                    for (int ma = 0; ma < 2; ma++) {
                        mma_f16(acc[ma][na], af[ma], b0h, b1h);
                    }
                }
            }
        }
        __syncthreads();
    }

    const float* bl = bias + (size_t)layer * D;
    const int q2 = (lane & 3) * 2;
    const int rq = lane >> 2;
#pragma unroll
    for (int na = 0; na < 8; na++) {
        int col = warpCol + na * 8 + q2;
        float2 bv = *(const float2*)(bl + col);
#pragma unroll
        for (int ma = 0; ma < 2; ma++) {
            float* c = acc[ma][na];
            long r0 = rowBase + warpRow + ma * 16 + rq;
#pragma unroll
            for (int h = 0; h < 2; h++) {
                long row = r0 + h * 8;
                if (row >= NN) continue;
                float ox = c[h * 2 + 0] + bv.x;
                float oy = c[h * 2 + 1] + bv.y;
                if (final_layer) {
                    *(float2*)(out + row * D + col) = make_float2(ox, oy);
                } else {
                    ox = fmaxf(ox, 0.f);
                    oy = fmaxf(oy, 0.f);
                    *(__half2*)(g_hx + (size_t)row * KK + col) =
                        __floats2half2_rn(ox, oy);
                }
            }
        }
    }
}

// ---------------------------------------------------------------
extern "C" void kernel_launch(void* const* d_in, const int* in_sizes, int n_in,
                              void* d_out, int out_size) {
    const float* emb = (const float*)d_in[0];
    const float* Ws  = (const float*)d_in[1];
    const float* Wn  = (const float*)d_in[2];
    const float* b   = (const float*)d_in[3];
    const int*   src = (const int*)d_in[4];
    const int*   dst = (const int*)d_in[5];
    float*       out = (float*)d_out;

    void* pdeg;
    cudaGetSymbolAddress(&pdeg, g_deg);

    cudaFuncSetAttribute(k_gemm, cudaFuncAttributeMaxDynamicSharedMemorySize,
                         3 * STAGE_SZ);

    // one-time conversions + CSR build
    k_cvtw<<<(3 * KK * D + 255) / 256, 256>>>(Ws, Wn);
    k_cvtx<<<(NN * 32 + 255) / 256, 256>>>((const float4*)emb);
    cudaMemsetAsync(pdeg, 0, NN * sizeof(int));
    k_count<<<(NE + 255) / 256, 256>>>(dst);
    k_part<<<SCAN_NB, 256>>>();
    k_scanp<<<1, 512>>>();
    k_write<<<SCAN_NB, 256>>>();
    k_fill<<<(NE + 255) / 256, 256>>>(src, dst);

    const int aggGrid  = (NN + 7) / 8;
    const int gemmGrid = (NN + 127) / 128;

    k_agg<<<aggGrid, 256>>>();
    k_gemm<<<gemmGrid, 256, 3 * STAGE_SZ>>>(out, b, 0, 0);

    k_agg<<<aggGrid, 256>>>();
    k_gemm<<<gemmGrid, 256, 3 * STAGE_SZ>>>(out, b, 1, 0);

    k_agg<<<aggGrid, 256>>>();
    k_gemm<<<gemmGrid, 256, 3 * STAGE_SZ>>>(out, b, 2, 1);
}